// round 8
// baseline (speedup 1.0000x reference)
#include <cuda_runtime.h>
#include <cuda_bf16.h>
#include <cstdint>

// ---------------- problem constants ----------------
#define BATCH   32
#define S_LEN   729
#define EMB     1152
#define NH      16
#define HD      72
#define QKV_N   (3 * EMB)          // 3456
#define ROWS    (BATCH * S_LEN)    // 23328
#define SCL2E   (0.11785113019775792f * 1.4426950408889634f)  // scale * log2(e)

// ---------------- scratch (no cudaMalloc allowed) ----------------
__device__ float         g_xr [(size_t)ROWS * EMB];     // x, tf32-rounded
__device__ float         g_wqt[(size_t)QKV_N * EMB];    // w_qkv^T [N][K], tf32-rounded
__device__ float         g_wot[(size_t)EMB * EMB];      // w_out^T [N][K], tf32-rounded
__device__ __nv_bfloat16 g_qh [(size_t)ROWS * QKV_N];   // qkv hi (for attention)
__device__ __nv_bfloat16 g_ql [(size_t)ROWS * QKV_N];   // qkv lo
__device__ float         g_att[(size_t)ROWS * EMB];     // attn out, tf32-rounded

// =====================================================================
// helpers
// =====================================================================
__device__ __forceinline__ uint32_t smem_u32(const void* p) {
    uint32_t a;
    asm("{ .reg .u64 t; cvta.to.shared.u64 t, %1; cvt.u32.u64 %0, t; }"
        : "=r"(a) : "l"(p));
    return a;
}
__device__ __forceinline__ void ldsm_x4(uint32_t& r0, uint32_t& r1,
                                        uint32_t& r2, uint32_t& r3, uint32_t addr) {
    asm volatile("ldmatrix.sync.aligned.m8n8.x4.shared.b16 {%0,%1,%2,%3}, [%4];"
                 : "=r"(r0), "=r"(r1), "=r"(r2), "=r"(r3) : "r"(addr));
}
__device__ __forceinline__ void ldsm_x4_t(uint32_t& r0, uint32_t& r1,
                                          uint32_t& r2, uint32_t& r3, uint32_t addr) {
    asm volatile("ldmatrix.sync.aligned.m8n8.x4.trans.shared.b16 {%0,%1,%2,%3}, [%4];"
                 : "=r"(r0), "=r"(r1), "=r"(r2), "=r"(r3) : "r"(addr));
}
// bf16 mma (attention)
__device__ __forceinline__ void mma16816(float* c, const uint32_t* a, const uint32_t* b) {
    asm volatile(
        "mma.sync.aligned.m16n8k16.row.col.f32.bf16.bf16.f32 "
        "{%0,%1,%2,%3}, {%4,%5,%6,%7}, {%8,%9}, {%0,%1,%2,%3};"
        : "+f"(c[0]), "+f"(c[1]), "+f"(c[2]), "+f"(c[3])
        : "r"(a[0]), "r"(a[1]), "r"(a[2]), "r"(a[3]), "r"(b[0]), "r"(b[1]));
}
// tf32 mma (GEMMs)
__device__ __forceinline__ void mma1688_tf32(float* c, const uint32_t* a,
                                             const uint32_t* b) {
    asm volatile(
        "mma.sync.aligned.m16n8k8.row.col.f32.tf32.tf32.f32 "
        "{%0,%1,%2,%3}, {%4,%5,%6,%7}, {%8,%9}, {%0,%1,%2,%3};"
        : "+f"(c[0]), "+f"(c[1]), "+f"(c[2]), "+f"(c[3])
        : "r"(a[0]), "r"(a[1]), "r"(a[2]), "r"(a[3]), "r"(b[0]), "r"(b[1]));
}
__device__ __forceinline__ float tf32r(float x) {
    uint32_t r;
    asm("cvt.rna.tf32.f32 %0, %1;" : "=r"(r) : "f"(x));
    return __uint_as_float(r);
}
__device__ __forceinline__ uint32_t packbf2(float x, float y) {
    __nv_bfloat162 t = __floats2bfloat162_rn(x, y);
    return *reinterpret_cast<uint32_t*>(&t);
}
#define STS64(addr, v) \
    asm volatile("st.shared.b64 [%0], %1;" :: "r"(addr), "l"(v) : "memory")

#define CPASYNC(dst, src, sz) \
    asm volatile("cp.async.cg.shared.global [%0], [%1], 16, %2;" \
                 :: "r"(dst), "l"(src), "r"(sz) : "memory")
#define CPCOMMIT() asm volatile("cp.async.commit_group;" ::: "memory")
#define CPWAIT0()  asm volatile("cp.async.wait_group 0;" ::: "memory")
#define CPWAIT1()  asm volatile("cp.async.wait_group 1;" ::: "memory")

// FFMA-only 2^t (no MUFU)
__device__ __forceinline__ float exp2_fast(float t) {
    t = fmaxf(t, -126.0f);
    float fi = floorf(t);
    float f = t - fi;
    float p = 0.00133335581f;
    p = fmaf(p, f, 0.00961812910f);
    p = fmaf(p, f, 0.0555041087f);
    p = fmaf(p, f, 0.240226507f);
    p = fmaf(p, f, 0.693147180f);
    p = fmaf(p, f, 1.0f);
    return __int_as_float(__float_as_int(p) + ((int)fi << 23));
}

// =====================================================================
// conversion kernels
// =====================================================================
__global__ __launch_bounds__(256) void round_rows(
    const float* __restrict__ X, float* __restrict__ R, size_t n4)
{
    size_t stride = (size_t)gridDim.x * 256;
    for (size_t i = (size_t)blockIdx.x * 256 + threadIdx.x; i < n4; i += stride) {
        float4 v = reinterpret_cast<const float4*>(X)[i];
        v.x = tf32r(v.x); v.y = tf32r(v.y); v.z = tf32r(v.z); v.w = tf32r(v.w);
        reinterpret_cast<float4*>(R)[i] = v;
    }
}

__global__ __launch_bounds__(256) void transp32(
    const float* __restrict__ W, float* __restrict__ T, int K, int N)
{
    __shared__ float t[32][33];
    const int n0 = blockIdx.x * 32, k0 = blockIdx.y * 32;
    const int tx = threadIdx.x & 31, ty = threadIdx.x >> 5;
    #pragma unroll
    for (int i = 0; i < 4; i++) {
        int kk = ty + i * 8;
        t[kk][tx] = W[(size_t)(k0 + kk) * N + n0 + tx];
    }
    __syncthreads();
    #pragma unroll
    for (int i = 0; i < 4; i++) {
        int nn = ty + i * 8;
        T[(size_t)(n0 + nn) * K + k0 + tx] = tf32r(t[tx][nn]);
    }
}

// =====================================================================
// single-pass TF32 GEMM, cp.async 3-stage ring, 1 barrier/chunk, 2 CTAs/SM
// =====================================================================
#define GK    32
#define ROWB  144                       // smem row stride bytes (32 f32 + 16B pad)
#define PLANE_B (128 * ROWB)            // 18432 B
#define OFS_A 0
#define OFS_B PLANE_B
#define STAGE_B (2 * PLANE_B)           // 36864
#define GEMM_DYN (3 * STAGE_B)          // 110592 -> 2 CTAs/SM

__device__ __forceinline__ void gemm_issue(
    const float* __restrict__ A, const float* __restrict__ Bt,
    int M, int K, int m0, int n0, int k0, uint32_t stage, int tid)
{
    #pragma unroll
    for (int i = 0; i < 4; i++) {
        int f  = tid + i * 256;          // 0..1023
        int r  = f >> 3;
        int sg = f & 7;
        uint32_t doff = (uint32_t)(r * ROWB + sg * 16);
        int ar = (m0 + r < M) ? (m0 + r) : (M - 1);
        int sz = (m0 + r < M) ? 16 : 0;
        CPASYNC(stage + OFS_A + doff, A + (size_t)ar * K + k0 + sg * 4, sz);
        CPASYNC(stage + OFS_B + doff, Bt + (size_t)(n0 + r) * K + k0 + sg * 4, 16);
    }
}

__global__ __launch_bounds__(256, 2) void gemm_tf32(
    const float* __restrict__ A, const float* __restrict__ Bt,
    const float* __restrict__ bias, float* __restrict__ Cf,
    __nv_bfloat16* __restrict__ Ch, __nv_bfloat16* __restrict__ Cl,
    int M, int N, int K)
{
    extern __shared__ __align__(16) char smem[];
    const uint32_t sbase = smem_u32(smem);

    const int tid  = threadIdx.x;
    const int wid  = tid >> 5;
    const int lane = tid & 31;
    const int wm   = wid >> 1;
    const int wn   = wid & 1;
    const int m0   = blockIdx.y * 128;
    const int n0   = blockIdx.x * 128;

    float acc[2][8][4];
    #pragma unroll
    for (int i = 0; i < 2; i++)
        #pragma unroll
        for (int j = 0; j < 8; j++)
            #pragma unroll
            for (int t = 0; t < 4; t++) acc[i][j][t] = 0.f;

    const int nchunk = K / GK;
    gemm_issue(A, Bt, M, K, m0, n0, 0, sbase, tid);
    CPCOMMIT();
    gemm_issue(A, Bt, M, K, m0, n0, GK, sbase + STAGE_B, tid);
    CPCOMMIT();

    const int a_row = lane & 15;
    const int a_cg  = lane >> 4;
    const int b_nrl = (lane & 7) + ((lane >> 4) << 3);
    const int b_kg  = (lane >> 3) & 1;

    int s_cur = 0;   // stage of chunk c
    for (int c = 0; c < nchunk; c++) {
        const uint32_t st = sbase + s_cur * STAGE_B;
        CPWAIT1();          // chunk c landed (c+1 may still be in flight)
        __syncthreads();    // all warps past chunk c-1 compute; smem visible

        // issue chunk c+2 into stage (c+2)%3 == (c-1)%3 (free since iter c-1)
        int s_nxt = s_cur + 2; if (s_nxt >= 3) s_nxt -= 3;
        if (c + 2 < nchunk)
            gemm_issue(A, Bt, M, K, m0, n0, (c + 2) * GK,
                       sbase + s_nxt * STAGE_B, tid);
        CPCOMMIT();         // unconditional: keeps group indexing aligned

        #pragma unroll
        for (int ks = 0; ks < 4; ks++) {
            const int k0b = ks * 32;
            uint32_t a[2][4];
            #pragma unroll
            for (int mt = 0; mt < 2; mt++) {
                int row = wm * 32 + mt * 16 + a_row;
                uint32_t addr = st + OFS_A + (uint32_t)(row * ROWB + k0b + a_cg * 16);
                ldsm_x4(a[mt][0], a[mt][1], a[mt][2], a[mt][3], addr);
            }
            #pragma unroll
            for (int npp = 0; npp < 4; npp++) {
                int n = wn * 64 + npp * 16 + b_nrl;
                uint32_t addr = st + OFS_B + (uint32_t)(n * ROWB + k0b + b_kg * 16);
                uint32_t b[4];
                ldsm_x4(b[0], b[1], b[2], b[3], addr);
                #pragma unroll
                for (int mt = 0; mt < 2; mt++) {
                    mma1688_tf32(acc[mt][2*npp],   a[mt], &b[0]);
                    mma1688_tf32(acc[mt][2*npp+1], a[mt], &b[2]);
                }
            }
        }
        s_cur++; if (s_cur >= 3) s_cur -= 3;
    }

    // ---- epilogue ----
    #pragma unroll
    for (int mt = 0; mt < 2; mt++) {
        #pragma unroll
        for (int nt = 0; nt < 8; nt++) {
            int r0 = m0 + wm * 32 + mt * 16 + (lane >> 2);
            int r1 = r0 + 8;
            int cc = n0 + wn * 64 + nt * 8 + ((lane & 3) << 1);
            float2 bv = *reinterpret_cast<const float2*>(bias + cc);
            float o0 = acc[mt][nt][0] + bv.x;
            float o1 = acc[mt][nt][1] + bv.y;
            float o2 = acc[mt][nt][2] + bv.x;
            float o3 = acc[mt][nt][3] + bv.y;
            if (Cf) {
                if (r0 < M)
                    *reinterpret_cast<float2*>(Cf + (size_t)r0 * N + cc) = make_float2(o0, o1);
                if (r1 < M)
                    *reinterpret_cast<float2*>(Cf + (size_t)r1 * N + cc) = make_float2(o2, o3);
            } else {
                if (r0 < M) {
                    float h0 = __bfloat162float(__float2bfloat16(o0));
                    float h1 = __bfloat162float(__float2bfloat16(o1));
                    *reinterpret_cast<uint32_t*>(Ch + (size_t)r0 * N + cc) = packbf2(h0, h1);
                    *reinterpret_cast<uint32_t*>(Cl + (size_t)r0 * N + cc) =
                        packbf2(o0 - h0, o1 - h1);
                }
                if (r1 < M) {
                    float h2 = __bfloat162float(__float2bfloat16(o2));
                    float h3 = __bfloat162float(__float2bfloat16(o3));
                    *reinterpret_cast<uint32_t*>(Ch + (size_t)r1 * N + cc) = packbf2(h2, h3);
                    *reinterpret_cast<uint32_t*>(Cl + (size_t)r1 * N + cc) =
                        packbf2(o2 - h2, o3 - h3);
                }
            }
        }
    }
}

// =====================================================================
// tensor-core flash attention (bf16 3-split), double-buffered K/V
// smem: Q hi/lo + 2 x {Kh,Kl,Vh,Vl} = 10 tiles
// =====================================================================
#define ATS   88
#define AROWB (ATS * 2)
#define AT_TILE (64 * AROWB)             // 11264 B
#define AQH 0
#define AQL (1 * AT_TILE)
#define KVBASE(buf) ((2 + 4 * (buf)) * AT_TILE)
#define ATTN_DYN (10 * AT_TILE)          // 112640 -> 2 CTAs/SM
#define NKT 12

__device__ __forceinline__ void attn_issue_kv(
    const __nv_bfloat16* __restrict__ qh, const __nv_bfloat16* __restrict__ ql,
    long rowbase, int kc, int vc, int kv0, uint32_t kvb, int tid)
{
    for (int i = tid; i < 64 * 9; i += 128) {
        int r = i / 9, sg = i - r * 9;
        int s = kv0 + r;
        int ar = (s < S_LEN) ? s : (S_LEN - 1);
        int sz = (s < S_LEN) ? 16 : 0;
        size_t gk = (rowbase + ar) * (size_t)QKV_N + kc + sg * 8;
        size_t gv = (rowbase + ar) * (size_t)QKV_N + vc + sg * 8;
        uint32_t doff = (uint32_t)(r * AROWB + sg * 16);
        CPASYNC(kvb + 0 * AT_TILE + doff, qh + gk, sz);
        CPASYNC(kvb + 1 * AT_TILE + doff, ql + gk, sz);
        CPASYNC(kvb + 2 * AT_TILE + doff, qh + gv, sz);
        CPASYNC(kvb + 3 * AT_TILE + doff, ql + gv, sz);
    }
}

__global__ __launch_bounds__(128, 2) void attn_mma(
    const __nv_bfloat16* __restrict__ qh, const __nv_bfloat16* __restrict__ ql,
    float* __restrict__ att)
{
    extern __shared__ __align__(16) char asmem[];
    const uint32_t sb = smem_u32(asmem);

    const int tid  = threadIdx.x;
    const int wid  = tid >> 5;
    const int lane = tid & 31;
    const int qt   = blockIdx.x;
    const int bh   = blockIdx.y;
    const int b    = bh >> 4;
    const int h    = bh & 15;
    const long rowbase = (long)b * S_LEN;
    const int  q0 = qt * 64;

    const int qc = h * HD;
    const int kc = EMB + h * HD;
    const int vc = 2 * EMB + h * HD;

    // zero pads (cols 72..79) for all 10 tiles
    for (int i = tid; i < 64 * 2 * 10; i += 128) {
        int t = i / 128;
        int r = (i & 127) >> 1;
        int g = i & 1;
        STS64(sb + t * AT_TILE + (uint32_t)(r * AROWB + (72 + g * 4) * 2), 0ull);
    }
    __syncthreads();

    // prologue: stage Q + tile0 (one group)
    for (int i = tid; i < 64 * 9; i += 128) {
        int r = i / 9, sg = i - r * 9;
        int s = q0 + r;
        int ar = (s < S_LEN) ? s : (S_LEN - 1);
        int sz = (s < S_LEN) ? 16 : 0;
        size_t goff = (rowbase + ar) * (size_t)QKV_N + qc + sg * 8;
        uint32_t doff = (uint32_t)(r * AROWB + sg * 16);
        CPASYNC(sb + AQH + doff, qh + goff, sz);
        CPASYNC(sb + AQL + doff, ql + goff, sz);
    }
    attn_issue_kv(qh, ql, rowbase, kc, vc, 0, sb + KVBASE(0), tid);
    CPCOMMIT();

    float m0 = -1e30f, m1 = -1e30f, l0 = 0.f, l1 = 0.f;
    float acc[9][4];
    #pragma unroll
    for (int nt = 0; nt < 9; nt++)
        #pragma unroll
        for (int t = 0; t < 4; t++) acc[nt][t] = 0.f;

    for (int kt = 0; kt < NKT; kt++) {
        const int kv0 = kt * 64;
        const uint32_t kvb = sb + KVBASE(kt & 1);

        CPWAIT0();          // tile kt (and Q on kt=0) landed
        __syncthreads();    // all warps past tile kt-1 compute; smem visible

        // prefetch tile kt+1 into the other buffer (computed at kt-1, now free)
        if (kt + 1 < NKT)
            attn_issue_kv(qh, ql, rowbase, kc, vc, (kt + 1) * 64,
                          sb + KVBASE((kt + 1) & 1), tid);
        CPCOMMIT();

        const uint32_t AKHb = kvb, AKLb = kvb + AT_TILE;
        const uint32_t AVHb = kvb + 2 * AT_TILE, AVLb = kvb + 3 * AT_TILE;

        // ---- S = Q K^T ----
        float s[8][4];
        #pragma unroll
        for (int nt = 0; nt < 8; nt++)
            #pragma unroll
            for (int t = 0; t < 4; t++) s[nt][t] = 0.f;

        #pragma unroll
        for (int kk = 0; kk < 5; kk++) {
            const int k0 = kk * 16;
            uint32_t qfh[4], qfl[4];
            {
                int row = wid * 16 + (lane & 15);
                int col = k0 + ((lane >> 4) << 3);
                uint32_t off = (uint32_t)(row * AROWB + col * 2);
                ldsm_x4(qfh[0], qfh[1], qfh[2], qfh[3], sb + AQH + off);
                ldsm_x4(qfl[0], qfl[1], qfl[2], qfl[3], sb + AQL + off);
            }
            #pragma unroll
            for (int np = 0; np < 4; np++) {
                int row = np * 16 + (lane & 7) + ((lane >> 4) << 3);
                int col = k0 + (((lane >> 3) & 1) << 3);
                uint32_t off = (uint32_t)(row * AROWB + col * 2);
                uint32_t kh[4], kl[4];
                ldsm_x4(kh[0], kh[1], kh[2], kh[3], AKHb + off);
                ldsm_x4(kl[0], kl[1], kl[2], kl[3], AKLb + off);
                mma16816(s[2*np],   qfh, &kh[0]);
                mma16816(s[2*np],   qfh, &kl[0]);
                mma16816(s[2*np],   qfl, &kh[0]);
                mma16816(s[2*np+1], qfh, &kh[2]);
                mma16816(s[2*np+1], qfh, &kl[2]);
                mma16816(s[2*np+1], qfl, &kh[2]);
            }
        }

        // ---- fragment softmax (log2 domain) ----
        float mx0 = -1e30f, mx1 = -1e30f;
        #pragma unroll
        for (int nt = 0; nt < 8; nt++) {
            int cg = kv0 + nt * 8 + ((lane & 3) << 1);
            s[nt][0] = (cg     < S_LEN) ? s[nt][0] * SCL2E : -1e30f;
            s[nt][1] = (cg + 1 < S_LEN) ? s[nt][1] * SCL2E : -1e30f;
            s[nt][2] = (cg     < S_LEN) ? s[nt][2] * SCL2E : -1e30f;
            s[nt][3] = (cg + 1 < S_LEN) ? s[nt][3] * SCL2E : -1e30f;
            mx0 = fmaxf(mx0, fmaxf(s[nt][0], s[nt][1]));
            mx1 = fmaxf(mx1, fmaxf(s[nt][2], s[nt][3]));
        }
        mx0 = fmaxf(mx0, __shfl_xor_sync(0xffffffffu, mx0, 1));
        mx0 = fmaxf(mx0, __shfl_xor_sync(0xffffffffu, mx0, 2));
        mx1 = fmaxf(mx1, __shfl_xor_sync(0xffffffffu, mx1, 1));
        mx1 = fmaxf(mx1, __shfl_xor_sync(0xffffffffu, mx1, 2));
        float mn0 = fmaxf(m0, mx0);
        float mn1 = fmaxf(m1, mx1);
        float r0 = exp2_fast(m0 - mn0);
        float r1 = exp2_fast(m1 - mn1);
        m0 = mn0; m1 = mn1;

        uint32_t aPh[4][4], aPl[4][4];
        float ps0 = 0.f, ps1 = 0.f;
        #pragma unroll
        for (int nt = 0; nt < 8; nt++) {
            float p0 = exp2_fast(s[nt][0] - m0);
            float p1 = exp2_fast(s[nt][1] - m0);
            float p2 = exp2_fast(s[nt][2] - m1);
            float p3 = exp2_fast(s[nt][3] - m1);
            ps0 += p0 + p1;
            ps1 += p2 + p3;
            float h0 = __bfloat162float(__float2bfloat16(p0));
            float h1 = __bfloat162float(__float2bfloat16(p1));
            float h2 = __bfloat162float(__float2bfloat16(p2));
            float h3 = __bfloat162float(__float2bfloat16(p3));
            int kk = nt >> 1, ix = (nt & 1) << 1;
            aPh[kk][ix]     = packbf2(h0, h1);
            aPh[kk][ix + 1] = packbf2(h2, h3);
            aPl[kk][ix]     = packbf2(p0 - h0, p1 - h1);
            aPl[kk][ix + 1] = packbf2(p2 - h2, p3 - h3);
        }
        l0 = l0 * r0 + ps0;
        l1 = l1 * r1 + ps1;
        #pragma unroll
        for (int nt = 0; nt < 9; nt++) {
            acc[nt][0] *= r0; acc[nt][1] *= r0;
            acc[nt][2] *= r1; acc[nt][3] *= r1;
        }

        // ---- O += P V ----
        #pragma unroll
        for (int kk = 0; kk < 4; kk++) {
            #pragma unroll
            for (int np = 0; np < 5; np++) {
                int krow = kk * 16 + (lane & 7) + (((lane >> 3) & 1) << 3);
                int ncol = np * 16 + ((lane >> 4) << 3);
                uint32_t off = (uint32_t)(krow * AROWB + ncol * 2);
                uint32_t vh[4], vl[4];
                ldsm_x4_t(vh[0], vh[1], vh[2], vh[3], AVHb + off);
                ldsm_x4_t(vl[0], vl[1], vl[2], vl[3], AVLb + off);
                int nt0 = 2 * np, nt1 = 2 * np + 1;
                mma16816(acc[nt0], aPh[kk], &vh[0]);
                mma16816(acc[nt0], aPh[kk], &vl[0]);
                mma16816(acc[nt0], aPl[kk], &vh[0]);
                if (nt1 < 9) {
                    mma16816(acc[nt1], aPh[kk], &vh[2]);
                    mma16816(acc[nt1], aPh[kk], &vl[2]);
                    mma16816(acc[nt1], aPl[kk], &vh[2]);
                }
            }
        }
    }

    l0 += __shfl_xor_sync(0xffffffffu, l0, 1);
    l0 += __shfl_xor_sync(0xffffffffu, l0, 2);
    l1 += __shfl_xor_sync(0xffffffffu, l1, 1);
    l1 += __shfl_xor_sync(0xffffffffu, l1, 2);
    float inv0 = 1.f / l0;
    float inv1 = 1.f / l1;

    int rg0 = q0 + wid * 16 + (lane >> 2);
    int rg1 = rg0 + 8;
    #pragma unroll
    for (int nt = 0; nt < 9; nt++) {
        int col = h * HD + nt * 8 + ((lane & 3) << 1);
        if (rg0 < S_LEN) {
            float2 o = make_float2(tf32r(acc[nt][0] * inv0), tf32r(acc[nt][1] * inv0));
            *reinterpret_cast<float2*>(att + (rowbase + rg0) * (size_t)EMB + col) = o;
        }
        if (rg1 < S_LEN) {
            float2 o = make_float2(tf32r(acc[nt][2] * inv1), tf32r(acc[nt][3] * inv1));
            *reinterpret_cast<float2*>(att + (rowbase + rg1) * (size_t)EMB + col) = o;
        }
    }
}

// ---------------- launch ----------------
extern "C" void kernel_launch(void* const* d_in, const int* in_sizes, int n_in,
                              void* d_out, int out_size)
{
    const float* x      = (const float*)d_in[0];
    const float* w_qkv  = (const float*)d_in[1];
    const float* b_qkv  = (const float*)d_in[2];
    const float* w_out  = (const float*)d_in[3];
    const float* b_out  = (const float*)d_in[4];
    float* out = (float*)d_out;

    void *xr, *wqt, *wot, *qh, *ql, *att;
    cudaGetSymbolAddress(&xr,  g_xr);
    cudaGetSymbolAddress(&wqt, g_wqt);
    cudaGetSymbolAddress(&wot, g_wot);
    cudaGetSymbolAddress(&qh,  g_qh);
    cudaGetSymbolAddress(&ql,  g_ql);
    cudaGetSymbolAddress(&att, g_att);

    cudaFuncSetAttribute(gemm_tf32,
                         cudaFuncAttributeMaxDynamicSharedMemorySize, GEMM_DYN);
    cudaFuncSetAttribute(attn_mma,
                         cudaFuncAttributeMaxDynamicSharedMemorySize, ATTN_DYN);

    // 0) conversions
    round_rows<<<4096, 256>>>(x, (float*)xr, (size_t)ROWS * EMB / 4);
    transp32<<<dim3(QKV_N / 32, EMB / 32), 256>>>(w_qkv, (float*)wqt, EMB, QKV_N);
    transp32<<<dim3(EMB / 32, EMB / 32), 256>>>(w_out, (float*)wot, EMB, EMB);

    // 1) QKV projection (tf32) -> bf16 hi/lo planes for attention
    {
        dim3 grid(QKV_N / 128, (ROWS + 127) / 128);
        gemm_tf32<<<grid, 256, GEMM_DYN>>>(
            (const float*)xr, (const float*)wqt, b_qkv,
            nullptr, (__nv_bfloat16*)qh, (__nv_bfloat16*)ql,
            ROWS, QKV_N, EMB);
    }
    // 2) attention -> fp32 att (tf32-rounded)
    {
        dim3 grid(NKT, BATCH * NH);
        attn_mma<<<grid, 128, ATTN_DYN>>>(
            (const __nv_bfloat16*)qh, (const __nv_bfloat16*)ql, (float*)att);
    }
    // 3) output projection (tf32) -> fp32 out
    {
        dim3 grid(EMB / 128, (ROWS + 127) / 128);
        gemm_tf32<<<grid, 256, GEMM_DYN>>>(
            (const float*)att, (const float*)wot, b_out,
            out, nullptr, nullptr,
            ROWS, EMB, EMB);
    }
}

// round 9
// speedup vs baseline: 1.0109x; 1.0109x over previous
#include <cuda_runtime.h>
#include <cuda_bf16.h>
#include <cstdint>

// ---------------- problem constants ----------------
#define BATCH   32
#define S_LEN   729
#define EMB     1152
#define NH      16
#define HD      72
#define QKV_N   (3 * EMB)          // 3456
#define ROWS    (BATCH * S_LEN)    // 23328
#define SCL2E   (0.11785113019775792f * 1.4426950408889634f)  // scale * log2(e)

// ---------------- scratch (no cudaMalloc allowed) ----------------
__device__ float         g_xr [(size_t)ROWS * EMB];     // x, tf32-rounded
__device__ float         g_wqt[(size_t)QKV_N * EMB];    // w_qkv^T [N][K], tf32-rounded
__device__ float         g_wot[(size_t)EMB * EMB];      // w_out^T [N][K], tf32-rounded
__device__ __nv_bfloat16 g_qh [(size_t)ROWS * QKV_N];   // qkv hi (for attention)
__device__ __nv_bfloat16 g_ql [(size_t)ROWS * QKV_N];   // qkv lo
__device__ float         g_att[(size_t)ROWS * EMB];     // attn out, tf32-rounded

// =====================================================================
// helpers
// =====================================================================
__device__ __forceinline__ uint32_t smem_u32(const void* p) {
    uint32_t a;
    asm("{ .reg .u64 t; cvta.to.shared.u64 t, %1; cvt.u32.u64 %0, t; }"
        : "=r"(a) : "l"(p));
    return a;
}
__device__ __forceinline__ void ldsm_x4(uint32_t& r0, uint32_t& r1,
                                        uint32_t& r2, uint32_t& r3, uint32_t addr) {
    asm volatile("ldmatrix.sync.aligned.m8n8.x4.shared.b16 {%0,%1,%2,%3}, [%4];"
                 : "=r"(r0), "=r"(r1), "=r"(r2), "=r"(r3) : "r"(addr));
}
__device__ __forceinline__ void ldsm_x4_t(uint32_t& r0, uint32_t& r1,
                                          uint32_t& r2, uint32_t& r3, uint32_t addr) {
    asm volatile("ldmatrix.sync.aligned.m8n8.x4.trans.shared.b16 {%0,%1,%2,%3}, [%4];"
                 : "=r"(r0), "=r"(r1), "=r"(r2), "=r"(r3) : "r"(addr));
}
// bf16 mma (attention)
__device__ __forceinline__ void mma16816(float* c, const uint32_t* a, const uint32_t* b) {
    asm volatile(
        "mma.sync.aligned.m16n8k16.row.col.f32.bf16.bf16.f32 "
        "{%0,%1,%2,%3}, {%4,%5,%6,%7}, {%8,%9}, {%0,%1,%2,%3};"
        : "+f"(c[0]), "+f"(c[1]), "+f"(c[2]), "+f"(c[3])
        : "r"(a[0]), "r"(a[1]), "r"(a[2]), "r"(a[3]), "r"(b[0]), "r"(b[1]));
}
// tf32 mma (GEMMs)
__device__ __forceinline__ void mma1688_tf32(float* c, const uint32_t* a,
                                             const uint32_t* b) {
    asm volatile(
        "mma.sync.aligned.m16n8k8.row.col.f32.tf32.tf32.f32 "
        "{%0,%1,%2,%3}, {%4,%5,%6,%7}, {%8,%9}, {%0,%1,%2,%3};"
        : "+f"(c[0]), "+f"(c[1]), "+f"(c[2]), "+f"(c[3])
        : "r"(a[0]), "r"(a[1]), "r"(a[2]), "r"(a[3]), "r"(b[0]), "r"(b[1]));
}
__device__ __forceinline__ float tf32r(float x) {
    uint32_t r;
    asm("cvt.rna.tf32.f32 %0, %1;" : "=r"(r) : "f"(x));
    return __uint_as_float(r);
}
__device__ __forceinline__ uint32_t packbf2(float x, float y) {
    __nv_bfloat162 t = __floats2bfloat162_rn(x, y);
    return *reinterpret_cast<uint32_t*>(&t);
}
#define STS64(addr, v) \
    asm volatile("st.shared.b64 [%0], %1;" :: "r"(addr), "l"(v) : "memory")

#define CPASYNC(dst, src, sz) \
    asm volatile("cp.async.cg.shared.global [%0], [%1], 16, %2;" \
                 :: "r"(dst), "l"(src), "r"(sz) : "memory")
#define CPCOMMIT() asm volatile("cp.async.commit_group;" ::: "memory")
#define CPWAIT0()  asm volatile("cp.async.wait_group 0;" ::: "memory")
#define CPWAIT1()  asm volatile("cp.async.wait_group 1;" ::: "memory")

// FFMA-only 2^t (no MUFU)
__device__ __forceinline__ float exp2_fast(float t) {
    t = fmaxf(t, -126.0f);
    float fi = floorf(t);
    float f = t - fi;
    float p = 0.00133335581f;
    p = fmaf(p, f, 0.00961812910f);
    p = fmaf(p, f, 0.0555041087f);
    p = fmaf(p, f, 0.240226507f);
    p = fmaf(p, f, 0.693147180f);
    p = fmaf(p, f, 1.0f);
    return __int_as_float(__float_as_int(p) + ((int)fi << 23));
}

// =====================================================================
// conversion kernels
// =====================================================================
__global__ __launch_bounds__(256) void round_rows(
    const float* __restrict__ X, float* __restrict__ R, size_t n4)
{
    size_t stride = (size_t)gridDim.x * 256;
    for (size_t i = (size_t)blockIdx.x * 256 + threadIdx.x; i < n4; i += stride) {
        float4 v = reinterpret_cast<const float4*>(X)[i];
        v.x = tf32r(v.x); v.y = tf32r(v.y); v.z = tf32r(v.z); v.w = tf32r(v.w);
        reinterpret_cast<float4*>(R)[i] = v;
    }
}

__global__ __launch_bounds__(256) void transp32(
    const float* __restrict__ W, float* __restrict__ T, int K, int N)
{
    __shared__ float t[32][33];
    const int n0 = blockIdx.x * 32, k0 = blockIdx.y * 32;
    const int tx = threadIdx.x & 31, ty = threadIdx.x >> 5;
    #pragma unroll
    for (int i = 0; i < 4; i++) {
        int kk = ty + i * 8;
        t[kk][tx] = W[(size_t)(k0 + kk) * N + n0 + tx];
    }
    __syncthreads();
    #pragma unroll
    for (int i = 0; i < 4; i++) {
        int nn = ty + i * 8;
        T[(size_t)(n0 + nn) * K + k0 + tx] = tf32r(t[tx][nn]);
    }
}

// =====================================================================
// single-pass TF32 GEMM, 3-stage smem ring + 2-deep fragment pipeline
// =====================================================================
#define GK    32
#define ROWB  144                       // smem row stride bytes (32 f32 + 16B pad)
#define PLANE_B (128 * ROWB)            // 18432 B
#define OFS_A 0
#define OFS_B PLANE_B
#define STAGE_B (2 * PLANE_B)           // 36864
#define GEMM_DYN (3 * STAGE_B)          // 110592 -> 2 CTAs/SM

__device__ __forceinline__ void gemm_issue(
    const float* __restrict__ A, const float* __restrict__ Bt,
    int M, int K, int m0, int n0, int k0, uint32_t stage, int tid)
{
    #pragma unroll
    for (int i = 0; i < 4; i++) {
        int f  = tid + i * 256;          // 0..1023
        int r  = f >> 3;
        int sg = f & 7;
        uint32_t doff = (uint32_t)(r * ROWB + sg * 16);
        int ar = (m0 + r < M) ? (m0 + r) : (M - 1);
        int sz = (m0 + r < M) ? 16 : 0;
        CPASYNC(stage + OFS_A + doff, A + (size_t)ar * K + k0 + sg * 4, sz);
        CPASYNC(stage + OFS_B + doff, Bt + (size_t)(n0 + r) * K + k0 + sg * 4, 16);
    }
}

// load all 6 fragments (2 A + 4 B-pairs) for one k-step
__device__ __forceinline__ void load_frags(
    uint32_t st, int k0b, int wm, int wn,
    int a_row, int a_cg, int b_nrl, int b_kg,
    uint32_t a[2][4], uint32_t b[4][4])
{
    #pragma unroll
    for (int mt = 0; mt < 2; mt++) {
        int row = wm * 32 + mt * 16 + a_row;
        uint32_t addr = st + OFS_A + (uint32_t)(row * ROWB + k0b + a_cg * 16);
        ldsm_x4(a[mt][0], a[mt][1], a[mt][2], a[mt][3], addr);
    }
    #pragma unroll
    for (int npp = 0; npp < 4; npp++) {
        int n = wn * 64 + npp * 16 + b_nrl;
        uint32_t addr = st + OFS_B + (uint32_t)(n * ROWB + k0b + b_kg * 16);
        ldsm_x4(b[npp][0], b[npp][1], b[npp][2], b[npp][3], addr);
    }
}

__device__ __forceinline__ void do_mmas(float acc[2][8][4],
                                        uint32_t a[2][4], uint32_t b[4][4])
{
    #pragma unroll
    for (int npp = 0; npp < 4; npp++)
        #pragma unroll
        for (int mt = 0; mt < 2; mt++) {
            mma1688_tf32(acc[mt][2*npp],   a[mt], &b[npp][0]);
            mma1688_tf32(acc[mt][2*npp+1], a[mt], &b[npp][2]);
        }
}

__global__ __launch_bounds__(256, 2) void gemm_tf32(
    const float* __restrict__ A, const float* __restrict__ Bt,
    const float* __restrict__ bias, float* __restrict__ Cf,
    __nv_bfloat16* __restrict__ Ch, __nv_bfloat16* __restrict__ Cl,
    int M, int N, int K)
{
    extern __shared__ __align__(16) char smem[];
    const uint32_t sbase = smem_u32(smem);

    const int tid  = threadIdx.x;
    const int wid  = tid >> 5;
    const int lane = tid & 31;
    const int wm   = wid >> 1;
    const int wn   = wid & 1;
    const int m0   = blockIdx.y * 128;
    const int n0   = blockIdx.x * 128;

    float acc[2][8][4];
    #pragma unroll
    for (int i = 0; i < 2; i++)
        #pragma unroll
        for (int j = 0; j < 8; j++)
            #pragma unroll
            for (int t = 0; t < 4; t++) acc[i][j][t] = 0.f;

    const int nchunk = K / GK;
    gemm_issue(A, Bt, M, K, m0, n0, 0, sbase, tid);
    CPCOMMIT();
    gemm_issue(A, Bt, M, K, m0, n0, GK, sbase + STAGE_B, tid);
    CPCOMMIT();

    const int a_row = lane & 15;
    const int a_cg  = lane >> 4;
    const int b_nrl = (lane & 7) + ((lane >> 4) << 3);
    const int b_kg  = (lane >> 3) & 1;

    uint32_t fa[2][2][4], fb[2][4][4];   // 2-deep fragment pipeline

    int s_cur = 0;
    for (int c = 0; c < nchunk; c++) {
        const uint32_t st = sbase + s_cur * STAGE_B;
        CPWAIT1();          // chunk c landed (c+1 in flight)
        __syncthreads();

        // issue chunk c+2 into stage (c+2)%3 (free since iter c-1)
        int s_nxt = s_cur + 2; if (s_nxt >= 3) s_nxt -= 3;
        if (c + 2 < nchunk)
            gemm_issue(A, Bt, M, K, m0, n0, (c + 2) * GK,
                       sbase + s_nxt * STAGE_B, tid);
        CPCOMMIT();

        // fragment pipeline across the 4 k-steps of this chunk
        load_frags(st, 0, wm, wn, a_row, a_cg, b_nrl, b_kg, fa[0], fb[0]);
        #pragma unroll
        for (int ks = 0; ks < 4; ks++) {
            if (ks < 3)
                load_frags(st, (ks + 1) * 32, wm, wn, a_row, a_cg, b_nrl, b_kg,
                           fa[(ks + 1) & 1], fb[(ks + 1) & 1]);
            do_mmas(acc, fa[ks & 1], fb[ks & 1]);
        }

        s_cur++; if (s_cur >= 3) s_cur -= 3;
    }

    // ---- epilogue ----
    #pragma unroll
    for (int mt = 0; mt < 2; mt++) {
        #pragma unroll
        for (int nt = 0; nt < 8; nt++) {
            int r0 = m0 + wm * 32 + mt * 16 + (lane >> 2);
            int r1 = r0 + 8;
            int cc = n0 + wn * 64 + nt * 8 + ((lane & 3) << 1);
            float2 bv = *reinterpret_cast<const float2*>(bias + cc);
            float o0 = acc[mt][nt][0] + bv.x;
            float o1 = acc[mt][nt][1] + bv.y;
            float o2 = acc[mt][nt][2] + bv.x;
            float o3 = acc[mt][nt][3] + bv.y;
            if (Cf) {
                if (r0 < M)
                    *reinterpret_cast<float2*>(Cf + (size_t)r0 * N + cc) = make_float2(o0, o1);
                if (r1 < M)
                    *reinterpret_cast<float2*>(Cf + (size_t)r1 * N + cc) = make_float2(o2, o3);
            } else {
                if (r0 < M) {
                    float h0 = __bfloat162float(__float2bfloat16(o0));
                    float h1 = __bfloat162float(__float2bfloat16(o1));
                    *reinterpret_cast<uint32_t*>(Ch + (size_t)r0 * N + cc) = packbf2(h0, h1);
                    *reinterpret_cast<uint32_t*>(Cl + (size_t)r0 * N + cc) =
                        packbf2(o0 - h0, o1 - h1);
                }
                if (r1 < M) {
                    float h2 = __bfloat162float(__float2bfloat16(o2));
                    float h3 = __bfloat162float(__float2bfloat16(o3));
                    *reinterpret_cast<uint32_t*>(Ch + (size_t)r1 * N + cc) = packbf2(h2, h3);
                    *reinterpret_cast<uint32_t*>(Cl + (size_t)r1 * N + cc) =
                        packbf2(o2 - h2, o3 - h3);
                }
            }
        }
    }
}

// =====================================================================
// tensor-core flash attention (bf16 3-split) — proven R7 configuration
// =====================================================================
#define ATS   88
#define AROWB (ATS * 2)
#define AT_TILE (64 * AROWB)
#define AQH 0
#define AQL (1 * AT_TILE)
#define AKH (2 * AT_TILE)
#define AKL (3 * AT_TILE)
#define AVH (4 * AT_TILE)
#define AVL (5 * AT_TILE)
#define ATTN_DYN (6 * AT_TILE)
#define NKT 12

__global__ __launch_bounds__(128, 2) void attn_mma(
    const __nv_bfloat16* __restrict__ qh, const __nv_bfloat16* __restrict__ ql,
    float* __restrict__ att)
{
    extern __shared__ __align__(16) char asmem[];
    const uint32_t sb = smem_u32(asmem);

    const int tid  = threadIdx.x;
    const int wid  = tid >> 5;
    const int lane = tid & 31;
    const int qt   = blockIdx.x;
    const int bh   = blockIdx.y;
    const int b    = bh >> 4;
    const int h    = bh & 15;
    const long rowbase = (long)b * S_LEN;
    const int  q0 = qt * 64;

    const int qc = h * HD;
    const int kc = EMB + h * HD;
    const int vc = 2 * EMB + h * HD;

    for (int i = tid; i < 64 * 2 * 6; i += 128) {
        int t = i / 128;
        int r = (i & 127) >> 1;
        int g = i & 1;
        STS64(sb + t * AT_TILE + (uint32_t)(r * AROWB + (72 + g * 4) * 2), 0ull);
    }
    for (int i = tid; i < 64 * 9; i += 128) {
        int r = i / 9, sg = i - r * 9;
        int s = q0 + r;
        int ar = (s < S_LEN) ? s : (S_LEN - 1);
        int sz = (s < S_LEN) ? 16 : 0;
        size_t goff = (rowbase + ar) * (size_t)QKV_N + qc + sg * 8;
        uint32_t doff = (uint32_t)(r * AROWB + sg * 16);
        CPASYNC(sb + AQH + doff, qh + goff, sz);
        CPASYNC(sb + AQL + doff, ql + goff, sz);
    }
    CPCOMMIT();

    float m0 = -1e30f, m1 = -1e30f, l0 = 0.f, l1 = 0.f;
    float acc[9][4];
    #pragma unroll
    for (int nt = 0; nt < 9; nt++)
        #pragma unroll
        for (int t = 0; t < 4; t++) acc[nt][t] = 0.f;

    for (int kt = 0; kt < NKT; kt++) {
        const int kv0 = kt * 64;
        __syncthreads();

        for (int i = tid; i < 64 * 9; i += 128) {
            int r = i / 9, sg = i - r * 9;
            int s = kv0 + r;
            int ar = (s < S_LEN) ? s : (S_LEN - 1);
            int sz = (s < S_LEN) ? 16 : 0;
            size_t gk = (rowbase + ar) * (size_t)QKV_N + kc + sg * 8;
            size_t gv = (rowbase + ar) * (size_t)QKV_N + vc + sg * 8;
            uint32_t doff = (uint32_t)(r * AROWB + sg * 16);
            CPASYNC(sb + AKH + doff, qh + gk, sz);
            CPASYNC(sb + AKL + doff, ql + gk, sz);
            CPASYNC(sb + AVH + doff, qh + gv, sz);
            CPASYNC(sb + AVL + doff, ql + gv, sz);
        }
        CPCOMMIT();
        CPWAIT0();
        __syncthreads();

        float s[8][4];
        #pragma unroll
        for (int nt = 0; nt < 8; nt++)
            #pragma unroll
            for (int t = 0; t < 4; t++) s[nt][t] = 0.f;

        #pragma unroll
        for (int kk = 0; kk < 5; kk++) {
            const int k0 = kk * 16;
            uint32_t qfh[4], qfl[4];
            {
                int row = wid * 16 + (lane & 15);
                int col = k0 + ((lane >> 4) << 3);
                uint32_t off = (uint32_t)(row * AROWB + col * 2);
                ldsm_x4(qfh[0], qfh[1], qfh[2], qfh[3], sb + AQH + off);
                ldsm_x4(qfl[0], qfl[1], qfl[2], qfl[3], sb + AQL + off);
            }
            #pragma unroll
            for (int np = 0; np < 4; np++) {
                int row = np * 16 + (lane & 7) + ((lane >> 4) << 3);
                int col = k0 + (((lane >> 3) & 1) << 3);
                uint32_t off = (uint32_t)(row * AROWB + col * 2);
                uint32_t kh[4], kl[4];
                ldsm_x4(kh[0], kh[1], kh[2], kh[3], sb + AKH + off);
                ldsm_x4(kl[0], kl[1], kl[2], kl[3], sb + AKL + off);
                mma16816(s[2*np],   qfh, &kh[0]);
                mma16816(s[2*np],   qfh, &kl[0]);
                mma16816(s[2*np],   qfl, &kh[0]);
                mma16816(s[2*np+1], qfh, &kh[2]);
                mma16816(s[2*np+1], qfh, &kl[2]);
                mma16816(s[2*np+1], qfl, &kh[2]);
            }
        }

        float mx0 = -1e30f, mx1 = -1e30f;
        #pragma unroll
        for (int nt = 0; nt < 8; nt++) {
            int cg = kv0 + nt * 8 + ((lane & 3) << 1);
            s[nt][0] = (cg     < S_LEN) ? s[nt][0] * SCL2E : -1e30f;
            s[nt][1] = (cg + 1 < S_LEN) ? s[nt][1] * SCL2E : -1e30f;
            s[nt][2] = (cg     < S_LEN) ? s[nt][2] * SCL2E : -1e30f;
            s[nt][3] = (cg + 1 < S_LEN) ? s[nt][3] * SCL2E : -1e30f;
            mx0 = fmaxf(mx0, fmaxf(s[nt][0], s[nt][1]));
            mx1 = fmaxf(mx1, fmaxf(s[nt][2], s[nt][3]));
        }
        mx0 = fmaxf(mx0, __shfl_xor_sync(0xffffffffu, mx0, 1));
        mx0 = fmaxf(mx0, __shfl_xor_sync(0xffffffffu, mx0, 2));
        mx1 = fmaxf(mx1, __shfl_xor_sync(0xffffffffu, mx1, 1));
        mx1 = fmaxf(mx1, __shfl_xor_sync(0xffffffffu, mx1, 2));
        float mn0 = fmaxf(m0, mx0);
        float mn1 = fmaxf(m1, mx1);
        float r0 = exp2_fast(m0 - mn0);
        float r1 = exp2_fast(m1 - mn1);
        m0 = mn0; m1 = mn1;

        uint32_t aPh[4][4], aPl[4][4];
        float ps0 = 0.f, ps1 = 0.f;
        #pragma unroll
        for (int nt = 0; nt < 8; nt++) {
            float p0 = exp2_fast(s[nt][0] - m0);
            float p1 = exp2_fast(s[nt][1] - m0);
            float p2 = exp2_fast(s[nt][2] - m1);
            float p3 = exp2_fast(s[nt][3] - m1);
            ps0 += p0 + p1;
            ps1 += p2 + p3;
            float h0 = __bfloat162float(__float2bfloat16(p0));
            float h1 = __bfloat162float(__float2bfloat16(p1));
            float h2 = __bfloat162float(__float2bfloat16(p2));
            float h3 = __bfloat162float(__float2bfloat16(p3));
            int kk = nt >> 1, ix = (nt & 1) << 1;
            aPh[kk][ix]     = packbf2(h0, h1);
            aPh[kk][ix + 1] = packbf2(h2, h3);
            aPl[kk][ix]     = packbf2(p0 - h0, p1 - h1);
            aPl[kk][ix + 1] = packbf2(p2 - h2, p3 - h3);
        }
        l0 = l0 * r0 + ps0;
        l1 = l1 * r1 + ps1;
        #pragma unroll
        for (int nt = 0; nt < 9; nt++) {
            acc[nt][0] *= r0; acc[nt][1] *= r0;
            acc[nt][2] *= r1; acc[nt][3] *= r1;
        }

        #pragma unroll
        for (int kk = 0; kk < 4; kk++) {
            #pragma unroll
            for (int np = 0; np < 5; np++) {
                int krow = kk * 16 + (lane & 7) + (((lane >> 3) & 1) << 3);
                int ncol = np * 16 + ((lane >> 4) << 3);
                uint32_t off = (uint32_t)(krow * AROWB + ncol * 2);
                uint32_t vh[4], vl[4];
                ldsm_x4_t(vh[0], vh[1], vh[2], vh[3], sb + AVH + off);
                ldsm_x4_t(vl[0], vl[1], vl[2], vl[3], sb + AVL + off);
                int nt0 = 2 * np, nt1 = 2 * np + 1;
                mma16816(acc[nt0], aPh[kk], &vh[0]);
                mma16816(acc[nt0], aPh[kk], &vl[0]);
                mma16816(acc[nt0], aPl[kk], &vh[0]);
                if (nt1 < 9) {
                    mma16816(acc[nt1], aPh[kk], &vh[2]);
                    mma16816(acc[nt1], aPh[kk], &vl[2]);
                    mma16816(acc[nt1], aPl[kk], &vh[2]);
                }
            }
        }
    }

    l0 += __shfl_xor_sync(0xffffffffu, l0, 1);
    l0 += __shfl_xor_sync(0xffffffffu, l0, 2);
    l1 += __shfl_xor_sync(0xffffffffu, l1, 1);
    l1 += __shfl_xor_sync(0xffffffffu, l1, 2);
    float inv0 = 1.f / l0;
    float inv1 = 1.f / l1;

    int rg0 = q0 + wid * 16 + (lane >> 2);
    int rg1 = rg0 + 8;
    #pragma unroll
    for (int nt = 0; nt < 9; nt++) {
        int col = h * HD + nt * 8 + ((lane & 3) << 1);
        if (rg0 < S_LEN) {
            float2 o = make_float2(tf32r(acc[nt][0] * inv0), tf32r(acc[nt][1] * inv0));
            *reinterpret_cast<float2*>(att + (rowbase + rg0) * (size_t)EMB + col) = o;
        }
        if (rg1 < S_LEN) {
            float2 o = make_float2(tf32r(acc[nt][2] * inv1), tf32r(acc[nt][3] * inv1));
            *reinterpret_cast<float2*>(att + (rowbase + rg1) * (size_t)EMB + col) = o;
        }
    }
}

// ---------------- launch ----------------
extern "C" void kernel_launch(void* const* d_in, const int* in_sizes, int n_in,
                              void* d_out, int out_size)
{
    const float* x      = (const float*)d_in[0];
    const float* w_qkv  = (const float*)d_in[1];
    const float* b_qkv  = (const float*)d_in[2];
    const float* w_out  = (const float*)d_in[3];
    const float* b_out  = (const float*)d_in[4];
    float* out = (float*)d_out;

    void *xr, *wqt, *wot, *qh, *ql, *att;
    cudaGetSymbolAddress(&xr,  g_xr);
    cudaGetSymbolAddress(&wqt, g_wqt);
    cudaGetSymbolAddress(&wot, g_wot);
    cudaGetSymbolAddress(&qh,  g_qh);
    cudaGetSymbolAddress(&ql,  g_ql);
    cudaGetSymbolAddress(&att, g_att);

    cudaFuncSetAttribute(gemm_tf32,
                         cudaFuncAttributeMaxDynamicSharedMemorySize, GEMM_DYN);
    cudaFuncSetAttribute(attn_mma,
                         cudaFuncAttributeMaxDynamicSharedMemorySize, ATTN_DYN);

    // 0) conversions
    round_rows<<<4096, 256>>>(x, (float*)xr, (size_t)ROWS * EMB / 4);
    transp32<<<dim3(QKV_N / 32, EMB / 32), 256>>>(w_qkv, (float*)wqt, EMB, QKV_N);
    transp32<<<dim3(EMB / 32, EMB / 32), 256>>>(w_out, (float*)wot, EMB, EMB);

    // 1) QKV projection (tf32) -> bf16 hi/lo planes for attention
    {
        dim3 grid(QKV_N / 128, (ROWS + 127) / 128);
        gemm_tf32<<<grid, 256, GEMM_DYN>>>(
            (const float*)xr, (const float*)wqt, b_qkv,
            nullptr, (__nv_bfloat16*)qh, (__nv_bfloat16*)ql,
            ROWS, QKV_N, EMB);
    }
    // 2) attention -> fp32 att (tf32-rounded)
    {
        dim3 grid(NKT, BATCH * NH);
        attn_mma<<<grid, 128, ATTN_DYN>>>(
            (const __nv_bfloat16*)qh, (const __nv_bfloat16*)ql, (float*)att);
    }
    // 3) output projection (tf32) -> fp32 out
    {
        dim3 grid(EMB / 128, (ROWS + 127) / 128);
        gemm_tf32<<<grid, 256, GEMM_DYN>>>(
            (const float*)att, (const float*)wot, b_out,
            out, nullptr, nullptr,
            ROWS, EMB, EMB);
    }
}

// round 10
// speedup vs baseline: 1.4497x; 1.4341x over previous
#include <cuda_runtime.h>
#include <cuda_bf16.h>
#include <cuda_fp16.h>
#include <cstdint>

// ---------------- problem constants ----------------
#define BATCH   32
#define S_LEN   729
#define EMB     1152
#define NH      16
#define HD      72
#define QKV_N   (3 * EMB)          // 3456
#define ROWS    (BATCH * S_LEN)    // 23328
#define SCL2E   (0.11785113019775792f * 1.4426950408889634f)  // scale * log2(e)

// ---------------- scratch (no cudaMalloc allowed) ----------------
__device__ __half         g_x16 [(size_t)ROWS * EMB];    // x, fp16
__device__ __half         g_wq16[(size_t)QKV_N * EMB];   // w_qkv^T [N][K] fp16
__device__ __half         g_wo16[(size_t)EMB * EMB];     // w_out^T [N][K] fp16
__device__ __nv_bfloat16  g_qh  [(size_t)ROWS * QKV_N];  // qkv hi (attention)
__device__ __nv_bfloat16  g_ql  [(size_t)ROWS * QKV_N];  // qkv lo
__device__ __half         g_at16[(size_t)ROWS * EMB];    // attn out, fp16

// =====================================================================
// helpers
// =====================================================================
__device__ __forceinline__ uint32_t smem_u32(const void* p) {
    uint32_t a;
    asm("{ .reg .u64 t; cvta.to.shared.u64 t, %1; cvt.u32.u64 %0, t; }"
        : "=r"(a) : "l"(p));
    return a;
}
__device__ __forceinline__ void ldsm_x4(uint32_t& r0, uint32_t& r1,
                                        uint32_t& r2, uint32_t& r3, uint32_t addr) {
    asm volatile("ldmatrix.sync.aligned.m8n8.x4.shared.b16 {%0,%1,%2,%3}, [%4];"
                 : "=r"(r0), "=r"(r1), "=r"(r2), "=r"(r3) : "r"(addr));
}
__device__ __forceinline__ void ldsm_x4_t(uint32_t& r0, uint32_t& r1,
                                          uint32_t& r2, uint32_t& r3, uint32_t addr) {
    asm volatile("ldmatrix.sync.aligned.m8n8.x4.trans.shared.b16 {%0,%1,%2,%3}, [%4];"
                 : "=r"(r0), "=r"(r1), "=r"(r2), "=r"(r3) : "r"(addr));
}
// bf16 mma (attention)
__device__ __forceinline__ void mma16816(float* c, const uint32_t* a, const uint32_t* b) {
    asm volatile(
        "mma.sync.aligned.m16n8k16.row.col.f32.bf16.bf16.f32 "
        "{%0,%1,%2,%3}, {%4,%5,%6,%7}, {%8,%9}, {%0,%1,%2,%3};"
        : "+f"(c[0]), "+f"(c[1]), "+f"(c[2]), "+f"(c[3])
        : "r"(a[0]), "r"(a[1]), "r"(a[2]), "r"(a[3]), "r"(b[0]), "r"(b[1]));
}
// fp16 mma (GEMMs) — same 11-bit mantissa as tf32, 2x rate
__device__ __forceinline__ void mma16816_f16(float* c, const uint32_t* a,
                                             const uint32_t* b) {
    asm volatile(
        "mma.sync.aligned.m16n8k16.row.col.f32.f16.f16.f32 "
        "{%0,%1,%2,%3}, {%4,%5,%6,%7}, {%8,%9}, {%0,%1,%2,%3};"
        : "+f"(c[0]), "+f"(c[1]), "+f"(c[2]), "+f"(c[3])
        : "r"(a[0]), "r"(a[1]), "r"(a[2]), "r"(a[3]), "r"(b[0]), "r"(b[1]));
}
__device__ __forceinline__ uint32_t packbf2(float x, float y) {
    __nv_bfloat162 t = __floats2bfloat162_rn(x, y);
    return *reinterpret_cast<uint32_t*>(&t);
}
__device__ __forceinline__ uint32_t packh2(float x, float y) {
    __half2 t = __floats2half2_rn(x, y);
    return *reinterpret_cast<uint32_t*>(&t);
}
#define STS64(addr, v) \
    asm volatile("st.shared.b64 [%0], %1;" :: "r"(addr), "l"(v) : "memory")

#define CPASYNC(dst, src, sz) \
    asm volatile("cp.async.cg.shared.global [%0], [%1], 16, %2;" \
                 :: "r"(dst), "l"(src), "r"(sz) : "memory")
#define CPCOMMIT() asm volatile("cp.async.commit_group;" ::: "memory")
#define CPWAIT0()  asm volatile("cp.async.wait_group 0;" ::: "memory")
#define CPWAIT1()  asm volatile("cp.async.wait_group 1;" ::: "memory")

// FFMA-only 2^t (no MUFU)
__device__ __forceinline__ float exp2_fast(float t) {
    t = fmaxf(t, -126.0f);
    float fi = floorf(t);
    float f = t - fi;
    float p = 0.00133335581f;
    p = fmaf(p, f, 0.00961812910f);
    p = fmaf(p, f, 0.0555041087f);
    p = fmaf(p, f, 0.240226507f);
    p = fmaf(p, f, 0.693147180f);
    p = fmaf(p, f, 1.0f);
    return __int_as_float(__float_as_int(p) + ((int)fi << 23));
}

// =====================================================================
// conversion kernels
// =====================================================================
// fp32 -> fp16 (rn), same layout
__global__ __launch_bounds__(256) void h16_rows(
    const float* __restrict__ X, __half* __restrict__ H, size_t n4)
{
    size_t stride = (size_t)gridDim.x * 256;
    for (size_t i = (size_t)blockIdx.x * 256 + threadIdx.x; i < n4; i += stride) {
        float4 v = reinterpret_cast<const float4*>(X)[i];
        uint32_t u0 = packh2(v.x, v.y);
        uint32_t u1 = packh2(v.z, v.w);
        reinterpret_cast<unsigned long long*>(H)[i] =
            ((unsigned long long)u1 << 32) | u0;
    }
}

// W[K][N] fp32 -> T[N][K] fp16 (tiled transpose)
__global__ __launch_bounds__(256) void transp16(
    const float* __restrict__ W, __half* __restrict__ T, int K, int N)
{
    __shared__ float t[32][33];
    const int n0 = blockIdx.x * 32, k0 = blockIdx.y * 32;
    const int tx = threadIdx.x & 31, ty = threadIdx.x >> 5;
    #pragma unroll
    for (int i = 0; i < 4; i++) {
        int kk = ty + i * 8;
        t[kk][tx] = W[(size_t)(k0 + kk) * N + n0 + tx];
    }
    __syncthreads();
    #pragma unroll
    for (int i = 0; i < 4; i++) {
        int nn = ty + i * 8;
        T[(size_t)(n0 + nn) * K + k0 + tx] = __float2half_rn(t[tx][nn]);
    }
}

// =====================================================================
// single-pass FP16 tensor-core GEMM, 3-stage cp.async ring, 2 CTAs/SM
// C = A @ Bt^T + bias; A[M,K] fp16, Bt[N,K] fp16. N%128==0, K%64==0.
// =====================================================================
#define GK    64                        // halves per chunk (128 B per row)
#define ROWB  144                       // smem row stride bytes (128 + 16 pad)
#define PLANE_B (128 * ROWB)            // 18432 B
#define OFS_A 0
#define OFS_B PLANE_B
#define STAGE_B (2 * PLANE_B)           // 36864
#define GEMM_DYN (3 * STAGE_B)          // 110592 -> 2 CTAs/SM

__device__ __forceinline__ void gemm_issue(
    const __half* __restrict__ A, const __half* __restrict__ Bt,
    int M, int K, int m0, int n0, int k0, uint32_t stage, int tid)
{
    #pragma unroll
    for (int i = 0; i < 4; i++) {
        int f  = tid + i * 256;          // 0..1023
        int r  = f >> 3;                 // row 0..127
        int sg = f & 7;                  // 16B segment (8 halves)
        uint32_t doff = (uint32_t)(r * ROWB + sg * 16);
        int ar = (m0 + r < M) ? (m0 + r) : (M - 1);
        int sz = (m0 + r < M) ? 16 : 0;
        CPASYNC(stage + OFS_A + doff, A + (size_t)ar * K + k0 + sg * 8, sz);
        CPASYNC(stage + OFS_B + doff, Bt + (size_t)(n0 + r) * K + k0 + sg * 8, 16);
    }
}

__global__ __launch_bounds__(256, 2) void gemm_fp16(
    const __half* __restrict__ A, const __half* __restrict__ Bt,
    const float* __restrict__ bias, float* __restrict__ Cf,
    __nv_bfloat16* __restrict__ Ch, __nv_bfloat16* __restrict__ Cl,
    int M, int N, int K)
{
    extern __shared__ __align__(16) char smem[];
    const uint32_t sbase = smem_u32(smem);

    const int tid  = threadIdx.x;
    const int wid  = tid >> 5;
    const int lane = tid & 31;
    const int wm   = wid >> 1;          // 0..3
    const int wn   = wid & 1;           // 0..1
    const int m0   = blockIdx.y * 128;
    const int n0   = blockIdx.x * 128;

    float acc[2][8][4];
    #pragma unroll
    for (int i = 0; i < 2; i++)
        #pragma unroll
        for (int j = 0; j < 8; j++)
            #pragma unroll
            for (int t = 0; t < 4; t++) acc[i][j][t] = 0.f;

    const int nchunk = K / GK;          // 18
    gemm_issue(A, Bt, M, K, m0, n0, 0, sbase, tid);
    CPCOMMIT();
    gemm_issue(A, Bt, M, K, m0, n0, GK, sbase + STAGE_B, tid);
    CPCOMMIT();

    int s_cur = 0;
    for (int c = 0; c < nchunk; c++) {
        const uint32_t st = sbase + s_cur * STAGE_B;
        CPWAIT1();          // chunk c landed (c+1 in flight)
        __syncthreads();

        int s_nxt = s_cur + 2; if (s_nxt >= 3) s_nxt -= 3;
        if (c + 2 < nchunk)
            gemm_issue(A, Bt, M, K, m0, n0, (c + 2) * GK,
                       sbase + s_nxt * STAGE_B, tid);
        CPCOMMIT();

        #pragma unroll
        for (int ks = 0; ks < 4; ks++) {     // 4 k-steps of 16 halves
            const int colb = ks * 32;        // k-step byte offset (16 halves)
            uint32_t a[2][4];
            #pragma unroll
            for (int mt = 0; mt < 2; mt++) {
                int row = wm * 32 + mt * 16 + (lane & 15);
                uint32_t addr = st + OFS_A +
                    (uint32_t)(row * ROWB + colb + ((lane >> 4) << 4));
                ldsm_x4(a[mt][0], a[mt][1], a[mt][2], a[mt][3], addr);
            }
            #pragma unroll
            for (int npp = 0; npp < 4; npp++) {
                int n = wn * 64 + npp * 16 + (lane & 7) + ((lane >> 4) << 3);
                uint32_t addr = st + OFS_B +
                    (uint32_t)(n * ROWB + colb + (((lane >> 3) & 1) << 4));
                uint32_t b[4];
                ldsm_x4(b[0], b[1], b[2], b[3], addr);
                #pragma unroll
                for (int mt = 0; mt < 2; mt++) {
                    mma16816_f16(acc[mt][2*npp],   a[mt], &b[0]);
                    mma16816_f16(acc[mt][2*npp+1], a[mt], &b[2]);
                }
            }
        }
        s_cur++; if (s_cur >= 3) s_cur -= 3;
    }

    // ---- epilogue ----
    #pragma unroll
    for (int mt = 0; mt < 2; mt++) {
        #pragma unroll
        for (int nt = 0; nt < 8; nt++) {
            int r0 = m0 + wm * 32 + mt * 16 + (lane >> 2);
            int r1 = r0 + 8;
            int cc = n0 + wn * 64 + nt * 8 + ((lane & 3) << 1);
            float2 bv = *reinterpret_cast<const float2*>(bias + cc);
            float o0 = acc[mt][nt][0] + bv.x;
            float o1 = acc[mt][nt][1] + bv.y;
            float o2 = acc[mt][nt][2] + bv.x;
            float o3 = acc[mt][nt][3] + bv.y;
            if (Cf) {
                if (r0 < M)
                    *reinterpret_cast<float2*>(Cf + (size_t)r0 * N + cc) = make_float2(o0, o1);
                if (r1 < M)
                    *reinterpret_cast<float2*>(Cf + (size_t)r1 * N + cc) = make_float2(o2, o3);
            } else {
                if (r0 < M) {
                    float h0 = __bfloat162float(__float2bfloat16(o0));
                    float h1 = __bfloat162float(__float2bfloat16(o1));
                    *reinterpret_cast<uint32_t*>(Ch + (size_t)r0 * N + cc) = packbf2(h0, h1);
                    *reinterpret_cast<uint32_t*>(Cl + (size_t)r0 * N + cc) =
                        packbf2(o0 - h0, o1 - h1);
                }
                if (r1 < M) {
                    float h2 = __bfloat162float(__float2bfloat16(o2));
                    float h3 = __bfloat162float(__float2bfloat16(o3));
                    *reinterpret_cast<uint32_t*>(Ch + (size_t)r1 * N + cc) = packbf2(h2, h3);
                    *reinterpret_cast<uint32_t*>(Cl + (size_t)r1 * N + cc) =
                        packbf2(o2 - h2, o3 - h3);
                }
            }
        }
    }
}

// =====================================================================
// tensor-core flash attention (bf16 3-split) — proven R7 configuration,
// epilogue writes fp16 for the out-projection
// =====================================================================
#define ATS   88
#define AROWB (ATS * 2)
#define AT_TILE (64 * AROWB)
#define AQH 0
#define AQL (1 * AT_TILE)
#define AKH (2 * AT_TILE)
#define AKL (3 * AT_TILE)
#define AVH (4 * AT_TILE)
#define AVL (5 * AT_TILE)
#define ATTN_DYN (6 * AT_TILE)
#define NKT 12

__global__ __launch_bounds__(128, 2) void attn_mma(
    const __nv_bfloat16* __restrict__ qh, const __nv_bfloat16* __restrict__ ql,
    __half* __restrict__ att)
{
    extern __shared__ __align__(16) char asmem[];
    const uint32_t sb = smem_u32(asmem);

    const int tid  = threadIdx.x;
    const int wid  = tid >> 5;
    const int lane = tid & 31;
    const int qt   = blockIdx.x;
    const int bh   = blockIdx.y;
    const int b    = bh >> 4;
    const int h    = bh & 15;
    const long rowbase = (long)b * S_LEN;
    const int  q0 = qt * 64;

    const int qc = h * HD;
    const int kc = EMB + h * HD;
    const int vc = 2 * EMB + h * HD;

    for (int i = tid; i < 64 * 2 * 6; i += 128) {
        int t = i / 128;
        int r = (i & 127) >> 1;
        int g = i & 1;
        STS64(sb + t * AT_TILE + (uint32_t)(r * AROWB + (72 + g * 4) * 2), 0ull);
    }
    for (int i = tid; i < 64 * 9; i += 128) {
        int r = i / 9, sg = i - r * 9;
        int s = q0 + r;
        int ar = (s < S_LEN) ? s : (S_LEN - 1);
        int sz = (s < S_LEN) ? 16 : 0;
        size_t goff = (rowbase + ar) * (size_t)QKV_N + qc + sg * 8;
        uint32_t doff = (uint32_t)(r * AROWB + sg * 16);
        CPASYNC(sb + AQH + doff, qh + goff, sz);
        CPASYNC(sb + AQL + doff, ql + goff, sz);
    }
    CPCOMMIT();

    float m0 = -1e30f, m1 = -1e30f, l0 = 0.f, l1 = 0.f;
    float acc[9][4];
    #pragma unroll
    for (int nt = 0; nt < 9; nt++)
        #pragma unroll
        for (int t = 0; t < 4; t++) acc[nt][t] = 0.f;

    for (int kt = 0; kt < NKT; kt++) {
        const int kv0 = kt * 64;
        __syncthreads();

        for (int i = tid; i < 64 * 9; i += 128) {
            int r = i / 9, sg = i - r * 9;
            int s = kv0 + r;
            int ar = (s < S_LEN) ? s : (S_LEN - 1);
            int sz = (s < S_LEN) ? 16 : 0;
            size_t gk = (rowbase + ar) * (size_t)QKV_N + kc + sg * 8;
            size_t gv = (rowbase + ar) * (size_t)QKV_N + vc + sg * 8;
            uint32_t doff = (uint32_t)(r * AROWB + sg * 16);
            CPASYNC(sb + AKH + doff, qh + gk, sz);
            CPASYNC(sb + AKL + doff, ql + gk, sz);
            CPASYNC(sb + AVH + doff, qh + gv, sz);
            CPASYNC(sb + AVL + doff, ql + gv, sz);
        }
        CPCOMMIT();
        CPWAIT0();
        __syncthreads();

        float s[8][4];
        #pragma unroll
        for (int nt = 0; nt < 8; nt++)
            #pragma unroll
            for (int t = 0; t < 4; t++) s[nt][t] = 0.f;

        #pragma unroll
        for (int kk = 0; kk < 5; kk++) {
            const int k0 = kk * 16;
            uint32_t qfh[4], qfl[4];
            {
                int row = wid * 16 + (lane & 15);
                int col = k0 + ((lane >> 4) << 3);
                uint32_t off = (uint32_t)(row * AROWB + col * 2);
                ldsm_x4(qfh[0], qfh[1], qfh[2], qfh[3], sb + AQH + off);
                ldsm_x4(qfl[0], qfl[1], qfl[2], qfl[3], sb + AQL + off);
            }
            #pragma unroll
            for (int np = 0; np < 4; np++) {
                int row = np * 16 + (lane & 7) + ((lane >> 4) << 3);
                int col = k0 + (((lane >> 3) & 1) << 3);
                uint32_t off = (uint32_t)(row * AROWB + col * 2);
                uint32_t kh[4], kl[4];
                ldsm_x4(kh[0], kh[1], kh[2], kh[3], sb + AKH + off);
                ldsm_x4(kl[0], kl[1], kl[2], kl[3], sb + AKL + off);
                mma16816(s[2*np],   qfh, &kh[0]);
                mma16816(s[2*np],   qfh, &kl[0]);
                mma16816(s[2*np],   qfl, &kh[0]);
                mma16816(s[2*np+1], qfh, &kh[2]);
                mma16816(s[2*np+1], qfh, &kl[2]);
                mma16816(s[2*np+1], qfl, &kh[2]);
            }
        }

        float mx0 = -1e30f, mx1 = -1e30f;
        #pragma unroll
        for (int nt = 0; nt < 8; nt++) {
            int cg = kv0 + nt * 8 + ((lane & 3) << 1);
            s[nt][0] = (cg     < S_LEN) ? s[nt][0] * SCL2E : -1e30f;
            s[nt][1] = (cg + 1 < S_LEN) ? s[nt][1] * SCL2E : -1e30f;
            s[nt][2] = (cg     < S_LEN) ? s[nt][2] * SCL2E : -1e30f;
            s[nt][3] = (cg + 1 < S_LEN) ? s[nt][3] * SCL2E : -1e30f;
            mx0 = fmaxf(mx0, fmaxf(s[nt][0], s[nt][1]));
            mx1 = fmaxf(mx1, fmaxf(s[nt][2], s[nt][3]));
        }
        mx0 = fmaxf(mx0, __shfl_xor_sync(0xffffffffu, mx0, 1));
        mx0 = fmaxf(mx0, __shfl_xor_sync(0xffffffffu, mx0, 2));
        mx1 = fmaxf(mx1, __shfl_xor_sync(0xffffffffu, mx1, 1));
        mx1 = fmaxf(mx1, __shfl_xor_sync(0xffffffffu, mx1, 2));
        float mn0 = fmaxf(m0, mx0);
        float mn1 = fmaxf(m1, mx1);
        float r0 = exp2_fast(m0 - mn0);
        float r1 = exp2_fast(m1 - mn1);
        m0 = mn0; m1 = mn1;

        uint32_t aPh[4][4], aPl[4][4];
        float ps0 = 0.f, ps1 = 0.f;
        #pragma unroll
        for (int nt = 0; nt < 8; nt++) {
            float p0 = exp2_fast(s[nt][0] - m0);
            float p1 = exp2_fast(s[nt][1] - m0);
            float p2 = exp2_fast(s[nt][2] - m1);
            float p3 = exp2_fast(s[nt][3] - m1);
            ps0 += p0 + p1;
            ps1 += p2 + p3;
            float h0 = __bfloat162float(__float2bfloat16(p0));
            float h1 = __bfloat162float(__float2bfloat16(p1));
            float h2 = __bfloat162float(__float2bfloat16(p2));
            float h3 = __bfloat162float(__float2bfloat16(p3));
            int kk = nt >> 1, ix = (nt & 1) << 1;
            aPh[kk][ix]     = packbf2(h0, h1);
            aPh[kk][ix + 1] = packbf2(h2, h3);
            aPl[kk][ix]     = packbf2(p0 - h0, p1 - h1);
            aPl[kk][ix + 1] = packbf2(p2 - h2, p3 - h3);
        }
        l0 = l0 * r0 + ps0;
        l1 = l1 * r1 + ps1;
        #pragma unroll
        for (int nt = 0; nt < 9; nt++) {
            acc[nt][0] *= r0; acc[nt][1] *= r0;
            acc[nt][2] *= r1; acc[nt][3] *= r1;
        }

        #pragma unroll
        for (int kk = 0; kk < 4; kk++) {
            #pragma unroll
            for (int np = 0; np < 5; np++) {
                int krow = kk * 16 + (lane & 7) + (((lane >> 3) & 1) << 3);
                int ncol = np * 16 + ((lane >> 4) << 3);
                uint32_t off = (uint32_t)(krow * AROWB + ncol * 2);
                uint32_t vh[4], vl[4];
                ldsm_x4_t(vh[0], vh[1], vh[2], vh[3], sb + AVH + off);
                ldsm_x4_t(vl[0], vl[1], vl[2], vl[3], sb + AVL + off);
                int nt0 = 2 * np, nt1 = 2 * np + 1;
                mma16816(acc[nt0], aPh[kk], &vh[0]);
                mma16816(acc[nt0], aPh[kk], &vl[0]);
                mma16816(acc[nt0], aPl[kk], &vh[0]);
                if (nt1 < 9) {
                    mma16816(acc[nt1], aPh[kk], &vh[2]);
                    mma16816(acc[nt1], aPh[kk], &vl[2]);
                    mma16816(acc[nt1], aPl[kk], &vh[2]);
                }
            }
        }
    }

    l0 += __shfl_xor_sync(0xffffffffu, l0, 1);
    l0 += __shfl_xor_sync(0xffffffffu, l0, 2);
    l1 += __shfl_xor_sync(0xffffffffu, l1, 1);
    l1 += __shfl_xor_sync(0xffffffffu, l1, 2);
    float inv0 = 1.f / l0;
    float inv1 = 1.f / l1;

    int rg0 = q0 + wid * 16 + (lane >> 2);
    int rg1 = rg0 + 8;
    #pragma unroll
    for (int nt = 0; nt < 9; nt++) {
        int col = h * HD + nt * 8 + ((lane & 3) << 1);
        if (rg0 < S_LEN) {
            *reinterpret_cast<uint32_t*>(att + (rowbase + rg0) * (size_t)EMB + col) =
                packh2(acc[nt][0] * inv0, acc[nt][1] * inv0);
        }
        if (rg1 < S_LEN) {
            *reinterpret_cast<uint32_t*>(att + (rowbase + rg1) * (size_t)EMB + col) =
                packh2(acc[nt][2] * inv1, acc[nt][3] * inv1);
        }
    }
}

// ---------------- launch ----------------
extern "C" void kernel_launch(void* const* d_in, const int* in_sizes, int n_in,
                              void* d_out, int out_size)
{
    const float* x      = (const float*)d_in[0];
    const float* w_qkv  = (const float*)d_in[1];
    const float* b_qkv  = (const float*)d_in[2];
    const float* w_out  = (const float*)d_in[3];
    const float* b_out  = (const float*)d_in[4];
    float* out = (float*)d_out;

    void *x16, *wq16, *wo16, *qh, *ql, *at16;
    cudaGetSymbolAddress(&x16,  g_x16);
    cudaGetSymbolAddress(&wq16, g_wq16);
    cudaGetSymbolAddress(&wo16, g_wo16);
    cudaGetSymbolAddress(&qh,   g_qh);
    cudaGetSymbolAddress(&ql,   g_ql);
    cudaGetSymbolAddress(&at16, g_at16);

    cudaFuncSetAttribute(gemm_fp16,
                         cudaFuncAttributeMaxDynamicSharedMemorySize, GEMM_DYN);
    cudaFuncSetAttribute(attn_mma,
                         cudaFuncAttributeMaxDynamicSharedMemorySize, ATTN_DYN);

    // 0) conversions: fp16-round x; transpose+fp16 weights
    h16_rows<<<4096, 256>>>(x, (__half*)x16, (size_t)ROWS * EMB / 4);
    transp16<<<dim3(QKV_N / 32, EMB / 32), 256>>>(w_qkv, (__half*)wq16, EMB, QKV_N);
    transp16<<<dim3(EMB / 32, EMB / 32), 256>>>(w_out, (__half*)wo16, EMB, EMB);

    // 1) QKV projection (fp16 single-pass) -> bf16 hi/lo planes for attention
    {
        dim3 grid(QKV_N / 128, (ROWS + 127) / 128);
        gemm_fp16<<<grid, 256, GEMM_DYN>>>(
            (const __half*)x16, (const __half*)wq16, b_qkv,
            nullptr, (__nv_bfloat16*)qh, (__nv_bfloat16*)ql,
            ROWS, QKV_N, EMB);
    }
    // 2) attention -> fp16 att
    {
        dim3 grid(NKT, BATCH * NH);
        attn_mma<<<grid, 128, ATTN_DYN>>>(
            (const __nv_bfloat16*)qh, (const __nv_bfloat16*)ql, (__half*)at16);
    }
    // 3) output projection (fp16 single-pass) -> fp32 out
    {
        dim3 grid(EMB / 128, (ROWS + 127) / 128);
        gemm_fp16<<<grid, 256, GEMM_DYN>>>(
            (const __half*)at16, (const __half*)wo16, b_out,
            out, nullptr, nullptr,
            ROWS, EMB, EMB);
    }
}

// round 11
// speedup vs baseline: 1.9887x; 1.3718x over previous
#include <cuda_runtime.h>
#include <cuda_bf16.h>
#include <cuda_fp16.h>
#include <cstdint>

// ---------------- problem constants ----------------
#define BATCH   32
#define S_LEN   729
#define EMB     1152
#define NH      16
#define HD      72
#define QKV_N   (3 * EMB)          // 3456
#define ROWS    (BATCH * S_LEN)    // 23328
#define SCL2E   (0.11785113019775792f * 1.4426950408889634f)  // scale * log2(e)

// ---------------- scratch (no cudaMalloc allowed) ----------------
__device__ __half g_x16 [(size_t)ROWS * EMB];    // x, fp16
__device__ __half g_wq16[(size_t)QKV_N * EMB];   // w_qkv^T [N][K] fp16
__device__ __half g_wo16[(size_t)EMB * EMB];     // w_out^T [N][K] fp16
__device__ __half g_q16 [(size_t)ROWS * QKV_N];  // qkv, fp16
__device__ __half g_at16[(size_t)ROWS * EMB];    // attn out, fp16

// =====================================================================
// helpers
// =====================================================================
__device__ __forceinline__ uint32_t smem_u32(const void* p) {
    uint32_t a;
    asm("{ .reg .u64 t; cvta.to.shared.u64 t, %1; cvt.u32.u64 %0, t; }"
        : "=r"(a) : "l"(p));
    return a;
}
__device__ __forceinline__ void ldsm_x4(uint32_t& r0, uint32_t& r1,
                                        uint32_t& r2, uint32_t& r3, uint32_t addr) {
    asm volatile("ldmatrix.sync.aligned.m8n8.x4.shared.b16 {%0,%1,%2,%3}, [%4];"
                 : "=r"(r0), "=r"(r1), "=r"(r2), "=r"(r3) : "r"(addr));
}
__device__ __forceinline__ void ldsm_x4_t(uint32_t& r0, uint32_t& r1,
                                          uint32_t& r2, uint32_t& r3, uint32_t addr) {
    asm volatile("ldmatrix.sync.aligned.m8n8.x4.trans.shared.b16 {%0,%1,%2,%3}, [%4];"
                 : "=r"(r0), "=r"(r1), "=r"(r2), "=r"(r3) : "r"(addr));
}
// fp16 mma, fp32 accumulate
__device__ __forceinline__ void mma16816_f16(float* c, const uint32_t* a,
                                             const uint32_t* b) {
    asm volatile(
        "mma.sync.aligned.m16n8k16.row.col.f32.f16.f16.f32 "
        "{%0,%1,%2,%3}, {%4,%5,%6,%7}, {%8,%9}, {%0,%1,%2,%3};"
        : "+f"(c[0]), "+f"(c[1]), "+f"(c[2]), "+f"(c[3])
        : "r"(a[0]), "r"(a[1]), "r"(a[2]), "r"(a[3]), "r"(b[0]), "r"(b[1]));
}
__device__ __forceinline__ uint32_t packh2(float x, float y) {
    __half2 t = __floats2half2_rn(x, y);
    return *reinterpret_cast<uint32_t*>(&t);
}
#define STS64(addr, v) \
    asm volatile("st.shared.b64 [%0], %1;" :: "r"(addr), "l"(v) : "memory")

#define CPASYNC(dst, src, sz) \
    asm volatile("cp.async.cg.shared.global [%0], [%1], 16, %2;" \
                 :: "r"(dst), "l"(src), "r"(sz) : "memory")
#define CPCOMMIT() asm volatile("cp.async.commit_group;" ::: "memory")
#define CPWAIT0()  asm volatile("cp.async.wait_group 0;" ::: "memory")
#define CPWAIT1()  asm volatile("cp.async.wait_group 1;" ::: "memory")

// FFMA-only 2^t (no MUFU)
__device__ __forceinline__ float exp2_fast(float t) {
    t = fmaxf(t, -126.0f);
    float fi = floorf(t);
    float f = t - fi;
    float p = 0.00133335581f;
    p = fmaf(p, f, 0.00961812910f);
    p = fmaf(p, f, 0.0555041087f);
    p = fmaf(p, f, 0.240226507f);
    p = fmaf(p, f, 0.693147180f);
    p = fmaf(p, f, 1.0f);
    return __int_as_float(__float_as_int(p) + ((int)fi << 23));
}

// =====================================================================
// conversion kernels
// =====================================================================
__global__ __launch_bounds__(256) void h16_rows(
    const float* __restrict__ X, __half* __restrict__ H, size_t n4)
{
    size_t stride = (size_t)gridDim.x * 256;
    for (size_t i = (size_t)blockIdx.x * 256 + threadIdx.x; i < n4; i += stride) {
        float4 v = reinterpret_cast<const float4*>(X)[i];
        uint32_t u0 = packh2(v.x, v.y);
        uint32_t u1 = packh2(v.z, v.w);
        reinterpret_cast<unsigned long long*>(H)[i] =
            ((unsigned long long)u1 << 32) | u0;
    }
}

__global__ __launch_bounds__(256) void transp16(
    const float* __restrict__ W, __half* __restrict__ T, int K, int N)
{
    __shared__ float t[32][33];
    const int n0 = blockIdx.x * 32, k0 = blockIdx.y * 32;
    const int tx = threadIdx.x & 31, ty = threadIdx.x >> 5;
    #pragma unroll
    for (int i = 0; i < 4; i++) {
        int kk = ty + i * 8;
        t[kk][tx] = W[(size_t)(k0 + kk) * N + n0 + tx];
    }
    __syncthreads();
    #pragma unroll
    for (int i = 0; i < 4; i++) {
        int nn = ty + i * 8;
        T[(size_t)(n0 + nn) * K + k0 + tx] = __float2half_rn(t[tx][nn]);
    }
}

// =====================================================================
// single-pass FP16 tensor-core GEMM, 3-stage cp.async ring, 2 CTAs/SM
// C = A @ Bt^T + bias;  fp32 out (Cf) or fp16 out (Ch16).
// =====================================================================
#define GK    64
#define ROWB  144
#define PLANE_B (128 * ROWB)
#define OFS_A 0
#define OFS_B PLANE_B
#define STAGE_B (2 * PLANE_B)           // 36864
#define GEMM_DYN (3 * STAGE_B)          // 110592 -> 2 CTAs/SM

__device__ __forceinline__ void gemm_issue(
    const __half* __restrict__ A, const __half* __restrict__ Bt,
    int M, int K, int m0, int n0, int k0, uint32_t stage, int tid)
{
    #pragma unroll
    for (int i = 0; i < 4; i++) {
        int f  = tid + i * 256;
        int r  = f >> 3;
        int sg = f & 7;
        uint32_t doff = (uint32_t)(r * ROWB + sg * 16);
        int ar = (m0 + r < M) ? (m0 + r) : (M - 1);
        int sz = (m0 + r < M) ? 16 : 0;
        CPASYNC(stage + OFS_A + doff, A + (size_t)ar * K + k0 + sg * 8, sz);
        CPASYNC(stage + OFS_B + doff, Bt + (size_t)(n0 + r) * K + k0 + sg * 8, 16);
    }
}

__global__ __launch_bounds__(256, 2) void gemm_fp16(
    const __half* __restrict__ A, const __half* __restrict__ Bt,
    const float* __restrict__ bias, float* __restrict__ Cf,
    __half* __restrict__ Ch16,
    int M, int N, int K)
{
    extern __shared__ __align__(16) char smem[];
    const uint32_t sbase = smem_u32(smem);

    const int tid  = threadIdx.x;
    const int wid  = tid >> 5;
    const int lane = tid & 31;
    const int wm   = wid >> 1;
    const int wn   = wid & 1;
    const int m0   = blockIdx.y * 128;
    const int n0   = blockIdx.x * 128;

    float acc[2][8][4];
    #pragma unroll
    for (int i = 0; i < 2; i++)
        #pragma unroll
        for (int j = 0; j < 8; j++)
            #pragma unroll
            for (int t = 0; t < 4; t++) acc[i][j][t] = 0.f;

    const int nchunk = K / GK;
    gemm_issue(A, Bt, M, K, m0, n0, 0, sbase, tid);
    CPCOMMIT();
    gemm_issue(A, Bt, M, K, m0, n0, GK, sbase + STAGE_B, tid);
    CPCOMMIT();

    int s_cur = 0;
    for (int c = 0; c < nchunk; c++) {
        const uint32_t st = sbase + s_cur * STAGE_B;
        CPWAIT1();
        __syncthreads();

        int s_nxt = s_cur + 2; if (s_nxt >= 3) s_nxt -= 3;
        if (c + 2 < nchunk)
            gemm_issue(A, Bt, M, K, m0, n0, (c + 2) * GK,
                       sbase + s_nxt * STAGE_B, tid);
        CPCOMMIT();

        #pragma unroll
        for (int ks = 0; ks < 4; ks++) {
            const int colb = ks * 32;
            uint32_t a[2][4];
            #pragma unroll
            for (int mt = 0; mt < 2; mt++) {
                int row = wm * 32 + mt * 16 + (lane & 15);
                uint32_t addr = st + OFS_A +
                    (uint32_t)(row * ROWB + colb + ((lane >> 4) << 4));
                ldsm_x4(a[mt][0], a[mt][1], a[mt][2], a[mt][3], addr);
            }
            #pragma unroll
            for (int npp = 0; npp < 4; npp++) {
                int n = wn * 64 + npp * 16 + (lane & 7) + ((lane >> 4) << 3);
                uint32_t addr = st + OFS_B +
                    (uint32_t)(n * ROWB + colb + (((lane >> 3) & 1) << 4));
                uint32_t b[4];
                ldsm_x4(b[0], b[1], b[2], b[3], addr);
                #pragma unroll
                for (int mt = 0; mt < 2; mt++) {
                    mma16816_f16(acc[mt][2*npp],   a[mt], &b[0]);
                    mma16816_f16(acc[mt][2*npp+1], a[mt], &b[2]);
                }
            }
        }
        s_cur++; if (s_cur >= 3) s_cur -= 3;
    }

    // ---- epilogue ----
    #pragma unroll
    for (int mt = 0; mt < 2; mt++) {
        #pragma unroll
        for (int nt = 0; nt < 8; nt++) {
            int r0 = m0 + wm * 32 + mt * 16 + (lane >> 2);
            int r1 = r0 + 8;
            int cc = n0 + wn * 64 + nt * 8 + ((lane & 3) << 1);
            float2 bv = *reinterpret_cast<const float2*>(bias + cc);
            float o0 = acc[mt][nt][0] + bv.x;
            float o1 = acc[mt][nt][1] + bv.y;
            float o2 = acc[mt][nt][2] + bv.x;
            float o3 = acc[mt][nt][3] + bv.y;
            if (Cf) {
                if (r0 < M)
                    *reinterpret_cast<float2*>(Cf + (size_t)r0 * N + cc) = make_float2(o0, o1);
                if (r1 < M)
                    *reinterpret_cast<float2*>(Cf + (size_t)r1 * N + cc) = make_float2(o2, o3);
            } else {
                if (r0 < M)
                    *reinterpret_cast<uint32_t*>(Ch16 + (size_t)r0 * N + cc) = packh2(o0, o1);
                if (r1 < M)
                    *reinterpret_cast<uint32_t*>(Ch16 + (size_t)r1 * N + cc) = packh2(o2, o3);
            }
        }
    }
}

// =====================================================================
// single-pass FP16 tensor-core flash attention
// smem: Q, K, V fp16 tiles (64 x 72, padded stride 88 halves)
// =====================================================================
#define ATS   88
#define AROWB (ATS * 2)
#define AT_TILE (64 * AROWB)             // 11264 B
#define AQ 0
#define AK (1 * AT_TILE)
#define AV (2 * AT_TILE)
#define ATTN_DYN (3 * AT_TILE)           // 33792 -> 3+ CTAs/SM
#define NKT 12

__global__ __launch_bounds__(128, 3) void attn_mma(
    const __half* __restrict__ qkv, __half* __restrict__ att)
{
    extern __shared__ __align__(16) char asmem[];
    const uint32_t sb = smem_u32(asmem);

    const int tid  = threadIdx.x;
    const int wid  = tid >> 5;
    const int lane = tid & 31;
    const int qt   = blockIdx.x;
    const int bh   = blockIdx.y;
    const int b    = bh >> 4;
    const int h    = bh & 15;
    const long rowbase = (long)b * S_LEN;
    const int  q0 = qt * 64;

    const int qc = h * HD;
    const int kc = EMB + h * HD;
    const int vc = 2 * EMB + h * HD;

    // zero pads (cols 72..79) for all 3 tiles
    for (int i = tid; i < 64 * 2 * 3; i += 128) {
        int t = i / 128;
        int r = (i & 127) >> 1;
        int g = i & 1;
        STS64(sb + t * AT_TILE + (uint32_t)(r * AROWB + (72 + g * 4) * 2), 0ull);
    }
    // stage Q (9 x 16B segs per row)
    for (int i = tid; i < 64 * 9; i += 128) {
        int r = i / 9, sg = i - r * 9;
        int s = q0 + r;
        int ar = (s < S_LEN) ? s : (S_LEN - 1);
        int sz = (s < S_LEN) ? 16 : 0;
        size_t goff = (rowbase + ar) * (size_t)QKV_N + qc + sg * 8;
        CPASYNC(sb + AQ + (uint32_t)(r * AROWB + sg * 16), qkv + goff, sz);
    }
    CPCOMMIT();

    float m0 = -1e30f, m1 = -1e30f, l0 = 0.f, l1 = 0.f;
    float acc[9][4];
    #pragma unroll
    for (int nt = 0; nt < 9; nt++)
        #pragma unroll
        for (int t = 0; t < 4; t++) acc[nt][t] = 0.f;

    for (int kt = 0; kt < NKT; kt++) {
        const int kv0 = kt * 64;
        __syncthreads();   // previous tile consumers done

        for (int i = tid; i < 64 * 9; i += 128) {
            int r = i / 9, sg = i - r * 9;
            int s = kv0 + r;
            int ar = (s < S_LEN) ? s : (S_LEN - 1);
            int sz = (s < S_LEN) ? 16 : 0;
            size_t gk = (rowbase + ar) * (size_t)QKV_N + kc + sg * 8;
            size_t gv = (rowbase + ar) * (size_t)QKV_N + vc + sg * 8;
            uint32_t doff = (uint32_t)(r * AROWB + sg * 16);
            CPASYNC(sb + AK + doff, qkv + gk, sz);
            CPASYNC(sb + AV + doff, qkv + gv, sz);
        }
        CPCOMMIT();
        CPWAIT0();
        __syncthreads();

        // ---- S = Q K^T (single-pass fp16) ----
        float s[8][4];
        #pragma unroll
        for (int nt = 0; nt < 8; nt++)
            #pragma unroll
            for (int t = 0; t < 4; t++) s[nt][t] = 0.f;

        #pragma unroll
        for (int kk = 0; kk < 5; kk++) {
            const int k0 = kk * 16;
            uint32_t qf[4];
            {
                int row = wid * 16 + (lane & 15);
                int col = k0 + ((lane >> 4) << 3);
                ldsm_x4(qf[0], qf[1], qf[2], qf[3],
                        sb + AQ + (uint32_t)(row * AROWB + col * 2));
            }
            #pragma unroll
            for (int np = 0; np < 4; np++) {
                int row = np * 16 + (lane & 7) + ((lane >> 4) << 3);
                int col = k0 + (((lane >> 3) & 1) << 3);
                uint32_t kf[4];
                ldsm_x4(kf[0], kf[1], kf[2], kf[3],
                        sb + AK + (uint32_t)(row * AROWB + col * 2));
                mma16816_f16(s[2*np],   qf, &kf[0]);
                mma16816_f16(s[2*np+1], qf, &kf[2]);
            }
        }

        // ---- fragment softmax (log2 domain) ----
        float mx0 = -1e30f, mx1 = -1e30f;
        #pragma unroll
        for (int nt = 0; nt < 8; nt++) {
            int cg = kv0 + nt * 8 + ((lane & 3) << 1);
            s[nt][0] = (cg     < S_LEN) ? s[nt][0] * SCL2E : -1e30f;
            s[nt][1] = (cg + 1 < S_LEN) ? s[nt][1] * SCL2E : -1e30f;
            s[nt][2] = (cg     < S_LEN) ? s[nt][2] * SCL2E : -1e30f;
            s[nt][3] = (cg + 1 < S_LEN) ? s[nt][3] * SCL2E : -1e30f;
            mx0 = fmaxf(mx0, fmaxf(s[nt][0], s[nt][1]));
            mx1 = fmaxf(mx1, fmaxf(s[nt][2], s[nt][3]));
        }
        mx0 = fmaxf(mx0, __shfl_xor_sync(0xffffffffu, mx0, 1));
        mx0 = fmaxf(mx0, __shfl_xor_sync(0xffffffffu, mx0, 2));
        mx1 = fmaxf(mx1, __shfl_xor_sync(0xffffffffu, mx1, 1));
        mx1 = fmaxf(mx1, __shfl_xor_sync(0xffffffffu, mx1, 2));
        float mn0 = fmaxf(m0, mx0);
        float mn1 = fmaxf(m1, mx1);
        float r0 = exp2_fast(m0 - mn0);
        float r1 = exp2_fast(m1 - mn1);
        m0 = mn0; m1 = mn1;

        uint32_t aP[4][4];
        float ps0 = 0.f, ps1 = 0.f;
        #pragma unroll
        for (int nt = 0; nt < 8; nt++) {
            float p0 = exp2_fast(s[nt][0] - m0);
            float p1 = exp2_fast(s[nt][1] - m0);
            float p2 = exp2_fast(s[nt][2] - m1);
            float p3 = exp2_fast(s[nt][3] - m1);
            ps0 += p0 + p1;
            ps1 += p2 + p3;
            int kk = nt >> 1, ix = (nt & 1) << 1;
            aP[kk][ix]     = packh2(p0, p1);
            aP[kk][ix + 1] = packh2(p2, p3);
        }
        l0 = l0 * r0 + ps0;
        l1 = l1 * r1 + ps1;
        #pragma unroll
        for (int nt = 0; nt < 9; nt++) {
            acc[nt][0] *= r0; acc[nt][1] *= r0;
            acc[nt][2] *= r1; acc[nt][3] *= r1;
        }

        // ---- O += P V (single-pass fp16) ----
        #pragma unroll
        for (int kk = 0; kk < 4; kk++) {
            #pragma unroll
            for (int np = 0; np < 5; np++) {
                int krow = kk * 16 + (lane & 7) + (((lane >> 3) & 1) << 3);
                int ncol = np * 16 + ((lane >> 4) << 3);
                uint32_t vf[4];
                ldsm_x4_t(vf[0], vf[1], vf[2], vf[3],
                          sb + AV + (uint32_t)(krow * AROWB + ncol * 2));
                int nt0 = 2 * np, nt1 = 2 * np + 1;
                mma16816_f16(acc[nt0], aP[kk], &vf[0]);
                if (nt1 < 9)
                    mma16816_f16(acc[nt1], aP[kk], &vf[2]);
            }
        }
    }

    // ---- finalize ----
    l0 += __shfl_xor_sync(0xffffffffu, l0, 1);
    l0 += __shfl_xor_sync(0xffffffffu, l0, 2);
    l1 += __shfl_xor_sync(0xffffffffu, l1, 1);
    l1 += __shfl_xor_sync(0xffffffffu, l1, 2);
    float inv0 = 1.f / l0;
    float inv1 = 1.f / l1;

    int rg0 = q0 + wid * 16 + (lane >> 2);
    int rg1 = rg0 + 8;
    #pragma unroll
    for (int nt = 0; nt < 9; nt++) {
        int col = h * HD + nt * 8 + ((lane & 3) << 1);
        if (rg0 < S_LEN) {
            *reinterpret_cast<uint32_t*>(att + (rowbase + rg0) * (size_t)EMB + col) =
                packh2(acc[nt][0] * inv0, acc[nt][1] * inv0);
        }
        if (rg1 < S_LEN) {
            *reinterpret_cast<uint32_t*>(att + (rowbase + rg1) * (size_t)EMB + col) =
                packh2(acc[nt][2] * inv1, acc[nt][3] * inv1);
        }
    }
}

// ---------------- launch ----------------
extern "C" void kernel_launch(void* const* d_in, const int* in_sizes, int n_in,
                              void* d_out, int out_size)
{
    const float* x      = (const float*)d_in[0];
    const float* w_qkv  = (const float*)d_in[1];
    const float* b_qkv  = (const float*)d_in[2];
    const float* w_out  = (const float*)d_in[3];
    const float* b_out  = (const float*)d_in[4];
    float* out = (float*)d_out;

    void *x16, *wq16, *wo16, *q16, *at16;
    cudaGetSymbolAddress(&x16,  g_x16);
    cudaGetSymbolAddress(&wq16, g_wq16);
    cudaGetSymbolAddress(&wo16, g_wo16);
    cudaGetSymbolAddress(&q16,  g_q16);
    cudaGetSymbolAddress(&at16, g_at16);

    cudaFuncSetAttribute(gemm_fp16,
                         cudaFuncAttributeMaxDynamicSharedMemorySize, GEMM_DYN);
    cudaFuncSetAttribute(attn_mma,
                         cudaFuncAttributeMaxDynamicSharedMemorySize, ATTN_DYN);

    // 0) conversions
    h16_rows<<<4096, 256>>>(x, (__half*)x16, (size_t)ROWS * EMB / 4);
    transp16<<<dim3(QKV_N / 32, EMB / 32), 256>>>(w_qkv, (__half*)wq16, EMB, QKV_N);
    transp16<<<dim3(EMB / 32, EMB / 32), 256>>>(w_out, (__half*)wo16, EMB, EMB);

    // 1) QKV projection (fp16) -> fp16 qkv plane
    {
        dim3 grid(QKV_N / 128, (ROWS + 127) / 128);
        gemm_fp16<<<grid, 256, GEMM_DYN>>>(
            (const __half*)x16, (const __half*)wq16, b_qkv,
            nullptr, (__half*)q16,
            ROWS, QKV_N, EMB);
    }
    // 2) attention (single-pass fp16) -> fp16 att
    {
        dim3 grid(NKT, BATCH * NH);
        attn_mma<<<grid, 128, ATTN_DYN>>>(
            (const __half*)q16, (__half*)at16);
    }
    // 3) output projection (fp16) -> fp32 out
    {
        dim3 grid(EMB / 128, (ROWS + 127) / 128);
        gemm_fp16<<<grid, 256, GEMM_DYN>>>(
            (const __half*)at16, (const __half*)wo16, b_out,
            out, nullptr,
            ROWS, EMB, EMB);
    }
}

// round 12
// speedup vs baseline: 1.9920x; 1.0017x over previous
#include <cuda_runtime.h>
#include <cuda_bf16.h>
#include <cuda_fp16.h>
#include <cstdint>

// ---------------- problem constants ----------------
#define BATCH   32
#define S_LEN   729
#define EMB     1152
#define NH      16
#define HD      72
#define QKV_N   (3 * EMB)          // 3456
#define ROWS    (BATCH * S_LEN)    // 23328
#define SCL2E   (0.11785113019775792f * 1.4426950408889634f)  // scale * log2(e)

// ---------------- scratch (no cudaMalloc allowed) ----------------
__device__ __half g_x16 [(size_t)ROWS * EMB];    // x, fp16
__device__ __half g_wq16[(size_t)QKV_N * EMB];   // w_qkv^T [N][K] fp16
__device__ __half g_wo16[(size_t)EMB * EMB];     // w_out^T [N][K] fp16
__device__ __half g_q16 [(size_t)ROWS * QKV_N];  // qkv, fp16
__device__ __half g_at16[(size_t)ROWS * EMB];    // attn out, fp16

// =====================================================================
// helpers
// =====================================================================
__device__ __forceinline__ uint32_t smem_u32(const void* p) {
    uint32_t a;
    asm("{ .reg .u64 t; cvta.to.shared.u64 t, %1; cvt.u32.u64 %0, t; }"
        : "=r"(a) : "l"(p));
    return a;
}
__device__ __forceinline__ void ldsm_x4(uint32_t& r0, uint32_t& r1,
                                        uint32_t& r2, uint32_t& r3, uint32_t addr) {
    asm volatile("ldmatrix.sync.aligned.m8n8.x4.shared.b16 {%0,%1,%2,%3}, [%4];"
                 : "=r"(r0), "=r"(r1), "=r"(r2), "=r"(r3) : "r"(addr));
}
__device__ __forceinline__ void ldsm_x4_t(uint32_t& r0, uint32_t& r1,
                                          uint32_t& r2, uint32_t& r3, uint32_t addr) {
    asm volatile("ldmatrix.sync.aligned.m8n8.x4.trans.shared.b16 {%0,%1,%2,%3}, [%4];"
                 : "=r"(r0), "=r"(r1), "=r"(r2), "=r"(r3) : "r"(addr));
}
// fp16 mma, fp32 accumulate
__device__ __forceinline__ void mma16816_f16(float* c, const uint32_t* a,
                                             const uint32_t* b) {
    asm volatile(
        "mma.sync.aligned.m16n8k16.row.col.f32.f16.f16.f32 "
        "{%0,%1,%2,%3}, {%4,%5,%6,%7}, {%8,%9}, {%0,%1,%2,%3};"
        : "+f"(c[0]), "+f"(c[1]), "+f"(c[2]), "+f"(c[3])
        : "r"(a[0]), "r"(a[1]), "r"(a[2]), "r"(a[3]), "r"(b[0]), "r"(b[1]));
}
__device__ __forceinline__ uint32_t packh2(float x, float y) {
    __half2 t = __floats2half2_rn(x, y);
    return *reinterpret_cast<uint32_t*>(&t);
}
#define STS64(addr, v) \
    asm volatile("st.shared.b64 [%0], %1;" :: "r"(addr), "l"(v) : "memory")

#define CPASYNC(dst, src, sz) \
    asm volatile("cp.async.cg.shared.global [%0], [%1], 16, %2;" \
                 :: "r"(dst), "l"(src), "r"(sz) : "memory")
#define CPCOMMIT() asm volatile("cp.async.commit_group;" ::: "memory")
#define CPWAIT0()  asm volatile("cp.async.wait_group 0;" ::: "memory")
#define CPWAIT1()  asm volatile("cp.async.wait_group 1;" ::: "memory")

// FFMA-only 2^t (no MUFU)
__device__ __forceinline__ float exp2_fast(float t) {
    t = fmaxf(t, -126.0f);
    float fi = floorf(t);
    float f = t - fi;
    float p = 0.00133335581f;
    p = fmaf(p, f, 0.00961812910f);
    p = fmaf(p, f, 0.0555041087f);
    p = fmaf(p, f, 0.240226507f);
    p = fmaf(p, f, 0.693147180f);
    p = fmaf(p, f, 1.0f);
    return __int_as_float(__float_as_int(p) + ((int)fi << 23));
}

// =====================================================================
// conversion kernels
// =====================================================================
__global__ __launch_bounds__(256) void h16_rows(
    const float* __restrict__ X, __half* __restrict__ H, size_t n4)
{
    size_t stride = (size_t)gridDim.x * 256;
    for (size_t i = (size_t)blockIdx.x * 256 + threadIdx.x; i < n4; i += stride) {
        float4 v = reinterpret_cast<const float4*>(X)[i];
        uint32_t u0 = packh2(v.x, v.y);
        uint32_t u1 = packh2(v.z, v.w);
        reinterpret_cast<unsigned long long*>(H)[i] =
            ((unsigned long long)u1 << 32) | u0;
    }
}

__global__ __launch_bounds__(256) void transp16(
    const float* __restrict__ W, __half* __restrict__ T, int K, int N)
{
    __shared__ float t[32][33];
    const int n0 = blockIdx.x * 32, k0 = blockIdx.y * 32;
    const int tx = threadIdx.x & 31, ty = threadIdx.x >> 5;
    #pragma unroll
    for (int i = 0; i < 4; i++) {
        int kk = ty + i * 8;
        t[kk][tx] = W[(size_t)(k0 + kk) * N + n0 + tx];
    }
    __syncthreads();
    #pragma unroll
    for (int i = 0; i < 4; i++) {
        int nn = ty + i * 8;
        T[(size_t)(n0 + nn) * K + k0 + tx] = __float2half_rn(t[tx][nn]);
    }
}

// =====================================================================
// single-pass FP16 tensor-core GEMM, 3-stage cp.async ring, 2 CTAs/SM,
// per-warp k-step rotation to de-phase LDSM vs HMMA bursts across warps
// =====================================================================
#define GK    64
#define ROWB  144
#define PLANE_B (128 * ROWB)
#define OFS_A 0
#define OFS_B PLANE_B
#define STAGE_B (2 * PLANE_B)           // 36864
#define GEMM_DYN (3 * STAGE_B)          // 110592 -> 2 CTAs/SM

__device__ __forceinline__ void gemm_issue(
    const __half* __restrict__ A, const __half* __restrict__ Bt,
    int M, int K, int m0, int n0, int k0, uint32_t stage, int tid)
{
    #pragma unroll
    for (int i = 0; i < 4; i++) {
        int f  = tid + i * 256;
        int r  = f >> 3;
        int sg = f & 7;
        uint32_t doff = (uint32_t)(r * ROWB + sg * 16);
        int ar = (m0 + r < M) ? (m0 + r) : (M - 1);
        int sz = (m0 + r < M) ? 16 : 0;
        CPASYNC(stage + OFS_A + doff, A + (size_t)ar * K + k0 + sg * 8, sz);
        CPASYNC(stage + OFS_B + doff, Bt + (size_t)(n0 + r) * K + k0 + sg * 8, 16);
    }
}

__global__ __launch_bounds__(256, 2) void gemm_fp16(
    const __half* __restrict__ A, const __half* __restrict__ Bt,
    const float* __restrict__ bias, float* __restrict__ Cf,
    __half* __restrict__ Ch16,
    int M, int N, int K)
{
    extern __shared__ __align__(16) char smem[];
    const uint32_t sbase = smem_u32(smem);

    const int tid  = threadIdx.x;
    const int wid  = tid >> 5;
    const int lane = tid & 31;
    const int wm   = wid >> 1;
    const int wn   = wid & 1;
    const int m0   = blockIdx.y * 128;
    const int n0   = blockIdx.x * 128;

    // per-warp k-step rotation: warps sharing an SMSP (wid, wid+4) get
    // different offsets -> their LDSM/HMMA phases interleave
    const int koff = (wid + ((wid >> 2) << 1)) & 3;

    float acc[2][8][4];
    #pragma unroll
    for (int i = 0; i < 2; i++)
        #pragma unroll
        for (int j = 0; j < 8; j++)
            #pragma unroll
            for (int t = 0; t < 4; t++) acc[i][j][t] = 0.f;

    const int nchunk = K / GK;
    gemm_issue(A, Bt, M, K, m0, n0, 0, sbase, tid);
    CPCOMMIT();
    gemm_issue(A, Bt, M, K, m0, n0, GK, sbase + STAGE_B, tid);
    CPCOMMIT();

    int s_cur = 0;
    for (int c = 0; c < nchunk; c++) {
        const uint32_t st = sbase + s_cur * STAGE_B;
        CPWAIT1();
        __syncthreads();

        int s_nxt = s_cur + 2; if (s_nxt >= 3) s_nxt -= 3;
        if (c + 2 < nchunk)
            gemm_issue(A, Bt, M, K, m0, n0, (c + 2) * GK,
                       sbase + s_nxt * STAGE_B, tid);
        CPCOMMIT();

        #pragma unroll
        for (int kk0 = 0; kk0 < 4; kk0++) {
            const int ks = (kk0 + koff) & 3;     // rotated k-step
            const int colb = ks * 32;
            uint32_t a[2][4];
            #pragma unroll
            for (int mt = 0; mt < 2; mt++) {
                int row = wm * 32 + mt * 16 + (lane & 15);
                uint32_t addr = st + OFS_A +
                    (uint32_t)(row * ROWB + colb + ((lane >> 4) << 4));
                ldsm_x4(a[mt][0], a[mt][1], a[mt][2], a[mt][3], addr);
            }
            #pragma unroll
            for (int npp = 0; npp < 4; npp++) {
                int n = wn * 64 + npp * 16 + (lane & 7) + ((lane >> 4) << 3);
                uint32_t addr = st + OFS_B +
                    (uint32_t)(n * ROWB + colb + (((lane >> 3) & 1) << 4));
                uint32_t b[4];
                ldsm_x4(b[0], b[1], b[2], b[3], addr);
                #pragma unroll
                for (int mt = 0; mt < 2; mt++) {
                    mma16816_f16(acc[mt][2*npp],   a[mt], &b[0]);
                    mma16816_f16(acc[mt][2*npp+1], a[mt], &b[2]);
                }
            }
        }
        s_cur++; if (s_cur >= 3) s_cur -= 3;
    }

    // ---- epilogue ----
    #pragma unroll
    for (int mt = 0; mt < 2; mt++) {
        #pragma unroll
        for (int nt = 0; nt < 8; nt++) {
            int r0 = m0 + wm * 32 + mt * 16 + (lane >> 2);
            int r1 = r0 + 8;
            int cc = n0 + wn * 64 + nt * 8 + ((lane & 3) << 1);
            float2 bv = *reinterpret_cast<const float2*>(bias + cc);
            float o0 = acc[mt][nt][0] + bv.x;
            float o1 = acc[mt][nt][1] + bv.y;
            float o2 = acc[mt][nt][2] + bv.x;
            float o3 = acc[mt][nt][3] + bv.y;
            if (Cf) {
                if (r0 < M)
                    *reinterpret_cast<float2*>(Cf + (size_t)r0 * N + cc) = make_float2(o0, o1);
                if (r1 < M)
                    *reinterpret_cast<float2*>(Cf + (size_t)r1 * N + cc) = make_float2(o2, o3);
            } else {
                if (r0 < M)
                    *reinterpret_cast<uint32_t*>(Ch16 + (size_t)r0 * N + cc) = packh2(o0, o1);
                if (r1 < M)
                    *reinterpret_cast<uint32_t*>(Ch16 + (size_t)r1 * N + cc) = packh2(o2, o3);
            }
        }
    }
}

// =====================================================================
// single-pass FP16 tensor-core flash attention (unchanged from R11)
// =====================================================================
#define ATS   88
#define AROWB (ATS * 2)
#define AT_TILE (64 * AROWB)             // 11264 B
#define AQ 0
#define AK (1 * AT_TILE)
#define AV (2 * AT_TILE)
#define ATTN_DYN (3 * AT_TILE)           // 33792 -> 3 CTAs/SM
#define NKT 12

__global__ __launch_bounds__(128, 3) void attn_mma(
    const __half* __restrict__ qkv, __half* __restrict__ att)
{
    extern __shared__ __align__(16) char asmem[];
    const uint32_t sb = smem_u32(asmem);

    const int tid  = threadIdx.x;
    const int wid  = tid >> 5;
    const int lane = tid & 31;
    const int qt   = blockIdx.x;
    const int bh   = blockIdx.y;
    const int b    = bh >> 4;
    const int h    = bh & 15;
    const long rowbase = (long)b * S_LEN;
    const int  q0 = qt * 64;

    const int qc = h * HD;
    const int kc = EMB + h * HD;
    const int vc = 2 * EMB + h * HD;

    for (int i = tid; i < 64 * 2 * 3; i += 128) {
        int t = i / 128;
        int r = (i & 127) >> 1;
        int g = i & 1;
        STS64(sb + t * AT_TILE + (uint32_t)(r * AROWB + (72 + g * 4) * 2), 0ull);
    }
    for (int i = tid; i < 64 * 9; i += 128) {
        int r = i / 9, sg = i - r * 9;
        int s = q0 + r;
        int ar = (s < S_LEN) ? s : (S_LEN - 1);
        int sz = (s < S_LEN) ? 16 : 0;
        size_t goff = (rowbase + ar) * (size_t)QKV_N + qc + sg * 8;
        CPASYNC(sb + AQ + (uint32_t)(r * AROWB + sg * 16), qkv + goff, sz);
    }
    CPCOMMIT();

    float m0 = -1e30f, m1 = -1e30f, l0 = 0.f, l1 = 0.f;
    float acc[9][4];
    #pragma unroll
    for (int nt = 0; nt < 9; nt++)
        #pragma unroll
        for (int t = 0; t < 4; t++) acc[nt][t] = 0.f;

    for (int kt = 0; kt < NKT; kt++) {
        const int kv0 = kt * 64;
        __syncthreads();

        for (int i = tid; i < 64 * 9; i += 128) {
            int r = i / 9, sg = i - r * 9;
            int s = kv0 + r;
            int ar = (s < S_LEN) ? s : (S_LEN - 1);
            int sz = (s < S_LEN) ? 16 : 0;
            size_t gk = (rowbase + ar) * (size_t)QKV_N + kc + sg * 8;
            size_t gv = (rowbase + ar) * (size_t)QKV_N + vc + sg * 8;
            uint32_t doff = (uint32_t)(r * AROWB + sg * 16);
            CPASYNC(sb + AK + doff, qkv + gk, sz);
            CPASYNC(sb + AV + doff, qkv + gv, sz);
        }
        CPCOMMIT();
        CPWAIT0();
        __syncthreads();

        float s[8][4];
        #pragma unroll
        for (int nt = 0; nt < 8; nt++)
            #pragma unroll
            for (int t = 0; t < 4; t++) s[nt][t] = 0.f;

        #pragma unroll
        for (int kk = 0; kk < 5; kk++) {
            const int k0 = kk * 16;
            uint32_t qf[4];
            {
                int row = wid * 16 + (lane & 15);
                int col = k0 + ((lane >> 4) << 3);
                ldsm_x4(qf[0], qf[1], qf[2], qf[3],
                        sb + AQ + (uint32_t)(row * AROWB + col * 2));
            }
            #pragma unroll
            for (int np = 0; np < 4; np++) {
                int row = np * 16 + (lane & 7) + ((lane >> 4) << 3);
                int col = k0 + (((lane >> 3) & 1) << 3);
                uint32_t kf[4];
                ldsm_x4(kf[0], kf[1], kf[2], kf[3],
                        sb + AK + (uint32_t)(row * AROWB + col * 2));
                mma16816_f16(s[2*np],   qf, &kf[0]);
                mma16816_f16(s[2*np+1], qf, &kf[2]);
            }
        }

        float mx0 = -1e30f, mx1 = -1e30f;
        #pragma unroll
        for (int nt = 0; nt < 8; nt++) {
            int cg = kv0 + nt * 8 + ((lane & 3) << 1);
            s[nt][0] = (cg     < S_LEN) ? s[nt][0] * SCL2E : -1e30f;
            s[nt][1] = (cg + 1 < S_LEN) ? s[nt][1] * SCL2E : -1e30f;
            s[nt][2] = (cg     < S_LEN) ? s[nt][2] * SCL2E : -1e30f;
            s[nt][3] = (cg + 1 < S_LEN) ? s[nt][3] * SCL2E : -1e30f;
            mx0 = fmaxf(mx0, fmaxf(s[nt][0], s[nt][1]));
            mx1 = fmaxf(mx1, fmaxf(s[nt][2], s[nt][3]));
        }
        mx0 = fmaxf(mx0, __shfl_xor_sync(0xffffffffu, mx0, 1));
        mx0 = fmaxf(mx0, __shfl_xor_sync(0xffffffffu, mx0, 2));
        mx1 = fmaxf(mx1, __shfl_xor_sync(0xffffffffu, mx1, 1));
        mx1 = fmaxf(mx1, __shfl_xor_sync(0xffffffffu, mx1, 2));
        float mn0 = fmaxf(m0, mx0);
        float mn1 = fmaxf(m1, mx1);
        float r0 = exp2_fast(m0 - mn0);
        float r1 = exp2_fast(m1 - mn1);
        m0 = mn0; m1 = mn1;

        uint32_t aP[4][4];
        float ps0 = 0.f, ps1 = 0.f;
        #pragma unroll
        for (int nt = 0; nt < 8; nt++) {
            float p0 = exp2_fast(s[nt][0] - m0);
            float p1 = exp2_fast(s[nt][1] - m0);
            float p2 = exp2_fast(s[nt][2] - m1);
            float p3 = exp2_fast(s[nt][3] - m1);
            ps0 += p0 + p1;
            ps1 += p2 + p3;
            int kk = nt >> 1, ix = (nt & 1) << 1;
            aP[kk][ix]     = packh2(p0, p1);
            aP[kk][ix + 1] = packh2(p2, p3);
        }
        l0 = l0 * r0 + ps0;
        l1 = l1 * r1 + ps1;
        #pragma unroll
        for (int nt = 0; nt < 9; nt++) {
            acc[nt][0] *= r0; acc[nt][1] *= r0;
            acc[nt][2] *= r1; acc[nt][3] *= r1;
        }

        #pragma unroll
        for (int kk = 0; kk < 4; kk++) {
            #pragma unroll
            for (int np = 0; np < 5; np++) {
                int krow = kk * 16 + (lane & 7) + (((lane >> 3) & 1) << 3);
                int ncol = np * 16 + ((lane >> 4) << 3);
                uint32_t vf[4];
                ldsm_x4_t(vf[0], vf[1], vf[2], vf[3],
                          sb + AV + (uint32_t)(krow * AROWB + ncol * 2));
                int nt0 = 2 * np, nt1 = 2 * np + 1;
                mma16816_f16(acc[nt0], aP[kk], &vf[0]);
                if (nt1 < 9)
                    mma16816_f16(acc[nt1], aP[kk], &vf[2]);
            }
        }
    }

    l0 += __shfl_xor_sync(0xffffffffu, l0, 1);
    l0 += __shfl_xor_sync(0xffffffffu, l0, 2);
    l1 += __shfl_xor_sync(0xffffffffu, l1, 1);
    l1 += __shfl_xor_sync(0xffffffffu, l1, 2);
    float inv0 = 1.f / l0;
    float inv1 = 1.f / l1;

    int rg0 = q0 + wid * 16 + (lane >> 2);
    int rg1 = rg0 + 8;
    #pragma unroll
    for (int nt = 0; nt < 9; nt++) {
        int col = h * HD + nt * 8 + ((lane & 3) << 1);
        if (rg0 < S_LEN) {
            *reinterpret_cast<uint32_t*>(att + (rowbase + rg0) * (size_t)EMB + col) =
                packh2(acc[nt][0] * inv0, acc[nt][1] * inv0);
        }
        if (rg1 < S_LEN) {
            *reinterpret_cast<uint32_t*>(att + (rowbase + rg1) * (size_t)EMB + col) =
                packh2(acc[nt][2] * inv1, acc[nt][3] * inv1);
        }
    }
}

// ---------------- launch ----------------
extern "C" void kernel_launch(void* const* d_in, const int* in_sizes, int n_in,
                              void* d_out, int out_size)
{
    const float* x      = (const float*)d_in[0];
    const float* w_qkv  = (const float*)d_in[1];
    const float* b_qkv  = (const float*)d_in[2];
    const float* w_out  = (const float*)d_in[3];
    const float* b_out  = (const float*)d_in[4];
    float* out = (float*)d_out;

    void *x16, *wq16, *wo16, *q16, *at16;
    cudaGetSymbolAddress(&x16,  g_x16);
    cudaGetSymbolAddress(&wq16, g_wq16);
    cudaGetSymbolAddress(&wo16, g_wo16);
    cudaGetSymbolAddress(&q16,  g_q16);
    cudaGetSymbolAddress(&at16, g_at16);

    cudaFuncSetAttribute(gemm_fp16,
                         cudaFuncAttributeMaxDynamicSharedMemorySize, GEMM_DYN);
    cudaFuncSetAttribute(attn_mma,
                         cudaFuncAttributeMaxDynamicSharedMemorySize, ATTN_DYN);

    // 0) conversions
    h16_rows<<<4096, 256>>>(x, (__half*)x16, (size_t)ROWS * EMB / 4);
    transp16<<<dim3(QKV_N / 32, EMB / 32), 256>>>(w_qkv, (__half*)wq16, EMB, QKV_N);
    transp16<<<dim3(EMB / 32, EMB / 32), 256>>>(w_out, (__half*)wo16, EMB, EMB);

    // 1) QKV projection (fp16) -> fp16 qkv plane
    {
        dim3 grid(QKV_N / 128, (ROWS + 127) / 128);
        gemm_fp16<<<grid, 256, GEMM_DYN>>>(
            (const __half*)x16, (const __half*)wq16, b_qkv,
            nullptr, (__half*)q16,
            ROWS, QKV_N, EMB);
    }
    // 2) attention (single-pass fp16) -> fp16 att
    {
        dim3 grid(NKT, BATCH * NH);
        attn_mma<<<grid, 128, ATTN_DYN>>>(
            (const __half*)q16, (__half*)at16);
    }
    // 3) output projection (fp16) -> fp32 out
    {
        dim3 grid(EMB / 128, (ROWS + 127) / 128);
        gemm_fp16<<<grid, 256, GEMM_DYN>>>(
            (const __half*)at16, (const __half*)wo16, b_out,
            out, nullptr,
            ROWS, EMB, EMB);
    }
}